// round 1
// baseline (speedup 1.0000x reference)
#include <cuda_runtime.h>
#include <math.h>

// Problem constants (fixed by the dataset)
#define NMAX 100000
#define EMAX 1600000
#define HDIM 128
#define NGRAPH 64
#define BN_EPS 1e-5f

// ---------------- static device scratch (no runtime allocation) ----------------
__device__ float g_emb[4ll * NMAX * HDIM];   // per-layer normalized outputs (concat storage)
__device__ float g_z[(size_t)NMAX * HDIM];   // aggregation output / gemm input
__device__ float g_t[(size_t)NMAX * HDIM];   // mlp intermediate
__device__ int   g_deg[NMAX];
__device__ int   g_cursor[NMAX];
__device__ int   g_rowptr[NMAX + 1];
__device__ int   g_csr[EMAX];
__device__ float g_bn[4 * 256];              // per layer: [0..127]=sum, [128..255]=sumsq
__device__ float g_pool[NGRAPH * 512];
__device__ float g_cnt[NGRAPH];

// ---------------- zero scratch that accumulates ----------------
__global__ void k_zero(int n) {
    int i = blockIdx.x * blockDim.x + threadIdx.x;
    int stride = gridDim.x * blockDim.x;
    for (int j = i; j < n; j += stride) { g_deg[j] = 0; g_cursor[j] = 0; }
    for (int j = i; j < 4 * 256; j += stride) g_bn[j] = 0.0f;
    for (int j = i; j < NGRAPH * 512; j += stride) g_pool[j] = 0.0f;
    for (int j = i; j < NGRAPH; j += stride) g_cnt[j] = 0.0f;
}

// ---------------- CSR build ----------------
__global__ void k_count(const int* __restrict__ dst, int e) {
    int i = blockIdx.x * blockDim.x + threadIdx.x;
    if (i < e) atomicAdd(&g_deg[dst[i]], 1);
}

// single-block exclusive scan of g_deg into g_rowptr
__global__ void k_scan(int n) {
    __shared__ int s[1024];
    int tid = threadIdx.x;
    int chunk = (n + 1023) / 1024;
    int start = tid * chunk;
    int end = min(start + chunk, n);
    int sum = 0;
    for (int i = start; i < end; i++) sum += g_deg[i];
    s[tid] = sum;
    __syncthreads();
    // Hillis-Steele inclusive scan (read phase / write phase separated by syncs)
    for (int off = 1; off < 1024; off <<= 1) {
        int v = (tid >= off) ? s[tid - off] : 0;
        __syncthreads();
        s[tid] += v;
        __syncthreads();
    }
    int base = (tid == 0) ? 0 : s[tid - 1];
    for (int i = start; i < end; i++) { g_rowptr[i] = base; base += g_deg[i]; }
    if (tid == 1023) g_rowptr[n] = base;
}

__global__ void k_fill(const int* __restrict__ src, const int* __restrict__ dst, int e) {
    int i = blockIdx.x * blockDim.x + threadIdx.x;
    if (i < e) {
        int d = dst[i];
        int pos = atomicAdd(&g_cursor[d], 1);
        g_csr[g_rowptr[d] + pos] = src[i];
    }
}

// ---------------- aggregation: z = (1+eps)*h + sum_{e: dst==n} h[src[e]] ----------------
// F=16 variant (layer 1): 16 threads per node
__global__ void k_agg16(const float* __restrict__ x, const float* __restrict__ eps_p, int n) {
    int gid = blockIdx.x * blockDim.x + threadIdx.x;
    int node = gid >> 4;
    int lane = gid & 15;
    if (node >= n) return;
    float eps1 = 1.0f + __ldg(eps_p);
    float acc = eps1 * __ldg(&x[(size_t)node * 16 + lane]);
    int s = g_rowptr[node], e = g_rowptr[node + 1];
    int i = s;
    for (; i + 4 <= e; i += 4) {
        int s0 = g_csr[i], s1 = g_csr[i + 1], s2 = g_csr[i + 2], s3 = g_csr[i + 3];
        acc += __ldg(&x[(size_t)s0 * 16 + lane]) + __ldg(&x[(size_t)s1 * 16 + lane]) +
               __ldg(&x[(size_t)s2 * 16 + lane]) + __ldg(&x[(size_t)s3 * 16 + lane]);
    }
    for (; i < e; i++) acc += __ldg(&x[(size_t)g_csr[i] * 16 + lane]);
    g_z[(size_t)node * 16 + lane] = acc;
}

// H=128 variant: one warp per node, float4 lanes, 4-way MLP unroll
__global__ void k_agg128(int layer_in, const float* __restrict__ eps_p, int n) {
    int warp = (blockIdx.x * blockDim.x + threadIdx.x) >> 5;
    int lane = threadIdx.x & 31;
    if (warp >= n) return;
    float eps1 = 1.0f + __ldg(eps_p);
    const float4* h4 = (const float4*)(g_emb + (size_t)layer_in * NMAX * HDIM);
    float4 self = h4[(size_t)warp * 32 + lane];
    float4 acc = make_float4(self.x * eps1, self.y * eps1, self.z * eps1, self.w * eps1);
    int s = g_rowptr[warp], e = g_rowptr[warp + 1];
    int i = s;
    for (; i + 4 <= e; i += 4) {
        int s0 = g_csr[i], s1 = g_csr[i + 1], s2 = g_csr[i + 2], s3 = g_csr[i + 3];
        float4 v0 = h4[(size_t)s0 * 32 + lane];
        float4 v1 = h4[(size_t)s1 * 32 + lane];
        float4 v2 = h4[(size_t)s2 * 32 + lane];
        float4 v3 = h4[(size_t)s3 * 32 + lane];
        acc.x += v0.x + v1.x + v2.x + v3.x;
        acc.y += v0.y + v1.y + v2.y + v3.y;
        acc.z += v0.z + v1.z + v2.z + v3.z;
        acc.w += v0.w + v1.w + v2.w + v3.w;
    }
    for (; i < e; i++) {
        float4 v = h4[(size_t)g_csr[i] * 32 + lane];
        acc.x += v.x; acc.y += v.y; acc.z += v.z; acc.w += v.w;
    }
    ((float4*)g_z)[(size_t)warp * 32 + lane] = acc;
}

// ---------------- SGEMM: C[n x 128] = relu(A[n x K] @ W[K x 128] + b) ----------------
// BM=128, BN=128, BK=16, 256 threads, 8x8 microtile
__global__ void __launch_bounds__(256, 2)
k_gemm_relu(const float* __restrict__ A, const float* __restrict__ W,
            const float* __restrict__ bias, float* __restrict__ C, int n, int K) {
    __shared__ float As[16][128];
    __shared__ float Ws[16][128];
    int row0 = blockIdx.x * 128;
    int tid = threadIdx.x;
    int tcol = tid & 15;   // 16 col groups of 8
    int trow = tid >> 4;   // 16 row groups of 8
    float acc[8][8];
#pragma unroll
    for (int i = 0; i < 8; i++)
#pragma unroll
        for (int j = 0; j < 8; j++) acc[i][j] = 0.0f;

    for (int kt = 0; kt < K; kt += 16) {
        // A tile: 128 rows x 16 cols, transposed into As[k][m]
#pragma unroll
        for (int l = 0; l < 2; l++) {
            int li = tid + l * 256;          // 0..511 float4 slots
            int m = li >> 2;                 // row in tile
            int kk = (li & 3) * 4;           // k start
            float4 v = make_float4(0.f, 0.f, 0.f, 0.f);
            int gr = row0 + m;
            if (gr < n) v = *(const float4*)&A[(size_t)gr * K + kt + kk];
            As[kk + 0][m] = v.x; As[kk + 1][m] = v.y;
            As[kk + 2][m] = v.z; As[kk + 3][m] = v.w;
        }
        // W tile: 16 rows x 128 cols
#pragma unroll
        for (int l = 0; l < 2; l++) {
            int li = tid + l * 256;
            int kk = li >> 5;                // 0..15
            int c = (li & 31) * 4;
            *(float4*)&Ws[kk][c] = *(const float4*)&W[(size_t)(kt + kk) * 128 + c];
        }
        __syncthreads();
#pragma unroll
        for (int bk = 0; bk < 16; bk++) {
            float a[8], w[8];
            float4 a0 = *(float4*)&As[bk][trow * 8];
            float4 a1 = *(float4*)&As[bk][trow * 8 + 4];
            float4 w0 = *(float4*)&Ws[bk][tcol * 8];
            float4 w1 = *(float4*)&Ws[bk][tcol * 8 + 4];
            a[0]=a0.x;a[1]=a0.y;a[2]=a0.z;a[3]=a0.w;a[4]=a1.x;a[5]=a1.y;a[6]=a1.z;a[7]=a1.w;
            w[0]=w0.x;w[1]=w0.y;w[2]=w0.z;w[3]=w0.w;w[4]=w1.x;w[5]=w1.y;w[6]=w1.z;w[7]=w1.w;
#pragma unroll
            for (int i = 0; i < 8; i++)
#pragma unroll
                for (int j = 0; j < 8; j++) acc[i][j] += a[i] * w[j];
        }
        __syncthreads();
    }
    float bj[8];
#pragma unroll
    for (int j = 0; j < 8; j++) bj[j] = bias[tcol * 8 + j];
#pragma unroll
    for (int i = 0; i < 8; i++) {
        int gr = row0 + trow * 8 + i;
        if (gr < n) {
            float4 o0, o1;
            o0.x = fmaxf(acc[i][0] + bj[0], 0.f); o0.y = fmaxf(acc[i][1] + bj[1], 0.f);
            o0.z = fmaxf(acc[i][2] + bj[2], 0.f); o0.w = fmaxf(acc[i][3] + bj[3], 0.f);
            o1.x = fmaxf(acc[i][4] + bj[4], 0.f); o1.y = fmaxf(acc[i][5] + bj[5], 0.f);
            o1.z = fmaxf(acc[i][6] + bj[6], 0.f); o1.w = fmaxf(acc[i][7] + bj[7], 0.f);
            *(float4*)&C[(size_t)gr * 128 + tcol * 8] = o0;
            *(float4*)&C[(size_t)gr * 128 + tcol * 8 + 4] = o1;
        }
    }
}

// ---------------- BatchNorm (training-mode batch stats) ----------------
__global__ void k_bn_stats(int layer, int n) {
    int f = threadIdx.x;   // 128 threads
    const float* u = g_emb + (size_t)layer * NMAX * HDIM;
    float s = 0.f, s2 = 0.f;
    for (int r = blockIdx.x; r < n; r += gridDim.x) {
        float v = u[(size_t)r * 128 + f];
        s += v;
        s2 += v * v;
    }
    atomicAdd(&g_bn[layer * 256 + f], s);
    atomicAdd(&g_bn[layer * 256 + 128 + f], s2);
}

__global__ void k_bn_apply(int layer, int n, const float* __restrict__ gamma,
                           const float* __restrict__ beta) {
    size_t idx = (size_t)blockIdx.x * blockDim.x + threadIdx.x;   // float4 index
    size_t total = (size_t)n * 32;
    if (idx >= total) return;
    int f4 = (int)(idx & 31);
    float inv_n = 1.0f / (float)n;
    float4* u = (float4*)(g_emb + (size_t)layer * NMAX * HDIM);
    float4 v = u[idx];
    const float* bs = &g_bn[layer * 256];
    float m0 = bs[f4*4+0]*inv_n, m1 = bs[f4*4+1]*inv_n, m2 = bs[f4*4+2]*inv_n, m3 = bs[f4*4+3]*inv_n;
    float r0 = rsqrtf(bs[128+f4*4+0]*inv_n - m0*m0 + BN_EPS);
    float r1 = rsqrtf(bs[128+f4*4+1]*inv_n - m1*m1 + BN_EPS);
    float r2 = rsqrtf(bs[128+f4*4+2]*inv_n - m2*m2 + BN_EPS);
    float r3 = rsqrtf(bs[128+f4*4+3]*inv_n - m3*m3 + BN_EPS);
    float4 ga = *(const float4*)&gamma[f4*4];
    float4 be = *(const float4*)&beta[f4*4];
    v.x = ga.x * (v.x - m0) * r0 + be.x;
    v.y = ga.y * (v.y - m1) * r1 + be.y;
    v.z = ga.z * (v.z - m2) * r2 + be.z;
    v.w = ga.w * (v.w - m3) * r3 + be.w;
    u[idx] = v;
}

// ---------------- per-graph mean pool (batch is sorted) ----------------
__global__ void k_pool(const int* __restrict__ batch, int n) {
    int f = threadIdx.x;            // 0..511 ; feature = slab*128 + col  (concat order)
    int slab = f >> 7, col = f & 127;
    int chunk = (n + gridDim.x - 1) / gridDim.x;
    int start = blockIdx.x * chunk;
    int end = min(start + chunk, n);
    if (start >= end) return;
    const float* base = g_emb + (size_t)slab * NMAX * HDIM;
    float acc = 0.f;
    int cnt = 0;
    int cur = batch[start];
    for (int i = start; i < end; i++) {
        int g = batch[i];
        if (g != cur) {
            atomicAdd(&g_pool[cur * 512 + f], acc);
            if (f == 0) atomicAdd(&g_cnt[cur], (float)cnt);
            acc = 0.f; cnt = 0; cur = g;
        }
        acc += base[(size_t)i * 128 + col];
        cnt++;
    }
    atomicAdd(&g_pool[cur * 512 + f], acc);
    if (f == 0) atomicAdd(&g_cnt[cur], (float)cnt);
}

// ---------------- classifier: 512 -> 256 -> 128 -> 128 -> 10, log_softmax ----------------
__global__ void k_classifier(const float* __restrict__ W1, const float* __restrict__ b1,
                             const float* __restrict__ W2, const float* __restrict__ b2,
                             const float* __restrict__ W3, const float* __restrict__ b3,
                             const float* __restrict__ W4, const float* __restrict__ b4,
                             float* __restrict__ out) {
    __shared__ float emb[512], h1[256], h2[128], h3[128], logits[10];
    int g = blockIdx.x;
    int tid = threadIdx.x;   // 256 threads
    float cnt = fmaxf(g_cnt[g], 1.0f);
    for (int f = tid; f < 512; f += 256) emb[f] = g_pool[g * 512 + f] / cnt;
    __syncthreads();
    {
        float a = b1[tid];
        for (int k = 0; k < 512; k++) a += emb[k] * W1[k * 256 + tid];
        h1[tid] = fmaxf(a, 0.f);
    }
    __syncthreads();
    if (tid < 128) {
        float a = b2[tid];
        for (int k = 0; k < 256; k++) a += h1[k] * W2[k * 128 + tid];
        h2[tid] = fmaxf(a, 0.f);
    }
    __syncthreads();
    if (tid < 128) {
        float a = b3[tid];
        for (int k = 0; k < 128; k++) a += h2[k] * W3[k * 128 + tid];
        h3[tid] = fmaxf(a, 0.f);
    }
    __syncthreads();
    if (tid < 10) {
        float a = b4[tid];
        for (int k = 0; k < 128; k++) a += h3[k] * W4[k * 10 + tid];
        logits[tid] = a;
    }
    __syncthreads();
    if (tid == 0) {
        float mx = logits[0];
        for (int c = 1; c < 10; c++) mx = fmaxf(mx, logits[c]);
        float se = 0.f;
        for (int c = 0; c < 10; c++) se += expf(logits[c] - mx);
        float lse = logf(se) + mx;
        for (int c = 0; c < 10; c++) out[g * 10 + c] = logits[c] - lse;
    }
}

// ---------------- launch orchestration ----------------
extern "C" void kernel_launch(void* const* d_in, const int* in_sizes, int n_in,
                              void* d_out, int out_size) {
    const float* x     = (const float*)d_in[0];
    const int*   ei    = (const int*)d_in[1];
    const int*   batch = (const int*)d_in[2];
    const float* c1W1 = (const float*)d_in[3];
    const float* c1b1 = (const float*)d_in[4];
    const float* c1W2 = (const float*)d_in[5];
    const float* c1b2 = (const float*)d_in[6];
    const float* c1g  = (const float*)d_in[7];
    const float* c1b  = (const float*)d_in[8];
    const float* c1e  = (const float*)d_in[9];
    const float* cW1  = (const float*)d_in[10];
    const float* cb1  = (const float*)d_in[11];
    const float* cW2  = (const float*)d_in[12];
    const float* cb2  = (const float*)d_in[13];
    const float* cg   = (const float*)d_in[14];
    const float* cb   = (const float*)d_in[15];
    const float* ce   = (const float*)d_in[16];
    const float* lW1 = (const float*)d_in[17];
    const float* lb1 = (const float*)d_in[18];
    const float* lW2 = (const float*)d_in[19];
    const float* lb2 = (const float*)d_in[20];
    const float* lW3 = (const float*)d_in[21];
    const float* lb3 = (const float*)d_in[22];
    const float* lW4 = (const float*)d_in[23];
    const float* lb4 = (const float*)d_in[24];
    float* out = (float*)d_out;

    int n = in_sizes[0] / 16;
    int e = in_sizes[1] / 2;
    if (n > NMAX) n = NMAX;
    if (e > EMAX) e = EMAX;
    const int* src = ei;
    const int* dst = ei + e;

    float* z_ptr;   cudaGetSymbolAddress((void**)&z_ptr, g_z);
    float* t_ptr;   cudaGetSymbolAddress((void**)&t_ptr, g_t);
    float* emb_ptr; cudaGetSymbolAddress((void**)&emb_ptr, g_emb);

    // 1. zero accumulators
    k_zero<<<256, 256>>>(n);
    // 2-4. CSR build
    k_count<<<(e + 255) / 256, 256>>>(dst, e);
    k_scan<<<1, 1024>>>(n);
    k_fill<<<(e + 255) / 256, 256>>>(src, dst, e);

    int gemm_blocks = (n + 127) / 128;

    // Layer 1 (F=16 input)
    k_agg16<<<(n * 16 + 255) / 256, 256>>>(x, c1e, n);
    k_gemm_relu<<<gemm_blocks, 256>>>(z_ptr, c1W1, c1b1, t_ptr, n, 16);
    k_gemm_relu<<<gemm_blocks, 256>>>(t_ptr, c1W2, c1b2, emb_ptr, n, 128);
    k_bn_stats<<<512, 128>>>(0, n);
    k_bn_apply<<<(n * 32 + 255) / 256, 256>>>(0, n, c1g, c1b);

    // Layers 2-4
    for (int l = 1; l < 4; l++) {
        int i = l - 1;
        k_agg128<<<(n * 32 + 255) / 256, 256>>>(l - 1, ce + i, n);
        k_gemm_relu<<<gemm_blocks, 256>>>(z_ptr, cW1 + (size_t)i * 128 * 128, cb1 + i * 128, t_ptr, n, 128);
        k_gemm_relu<<<gemm_blocks, 256>>>(t_ptr, cW2 + (size_t)i * 128 * 128, cb2 + i * 128,
                                          emb_ptr + (size_t)l * NMAX * HDIM, n, 128);
        k_bn_stats<<<512, 128>>>(l, n);
        k_bn_apply<<<(n * 32 + 255) / 256, 256>>>(l, n, cg + i * 128, cb + i * 128);
    }

    // pooling + classifier
    k_pool<<<200, 512>>>(batch, n);
    k_classifier<<<NGRAPH, 256>>>(lW1, lb1, lW2, lb2, lW3, lb3, lW4, lb4, out);
}

// round 3
// speedup vs baseline: 1.1754x; 1.1754x over previous
#include <cuda_runtime.h>
#include <cuda_fp16.h>
#include <math.h>

#define NMAX 100000
#define EMAX 1600000
#define HDIM 128
#define NGRAPH 64
#define BN_EPS 1e-5f

// ---------------- static device scratch ----------------
__device__ float  g_emb[4ll * NMAX * HDIM];    // raw (pre-BN) layer outputs, fp32
__device__ __half g_embh[4ll * NMAX * HDIM];   // fp16 mirror for gathers
__device__ float  g_z[(size_t)NMAX * HDIM];
__device__ float  g_t[(size_t)NMAX * HDIM];
__device__ int    g_deg[NMAX];
__device__ int    g_cursor[NMAX];
__device__ int    g_rowptr[NMAX + 1];
__device__ int    g_csr[EMAX];
__device__ float  g_bn[4 * 256];               // per layer: [0..127]=sum, [128..255]=sumsq
__device__ float  g_pool[NGRAPH * 512];
__device__ float  g_cnt[NGRAPH];

// ---------------- zero ----------------
__global__ void k_zero(int n) {
    int i = blockIdx.x * blockDim.x + threadIdx.x;
    int stride = gridDim.x * blockDim.x;
    for (int j = i; j < n; j += stride) { g_deg[j] = 0; g_cursor[j] = 0; }
    for (int j = i; j < 4 * 256; j += stride) g_bn[j] = 0.0f;
    for (int j = i; j < NGRAPH * 512; j += stride) g_pool[j] = 0.0f;
    for (int j = i; j < NGRAPH; j += stride) g_cnt[j] = 0.0f;
}

// ---------------- CSR build ----------------
__global__ void k_count(const int* __restrict__ dst, int e) {
    int i = blockIdx.x * blockDim.x + threadIdx.x;
    if (i < e) atomicAdd(&g_deg[dst[i]], 1);
}

__global__ void k_scan(int n) {
    __shared__ int s[1024];
    int tid = threadIdx.x;
    int chunk = (n + 1023) / 1024;
    int start = tid * chunk;
    int end = min(start + chunk, n);
    int sum = 0;
    for (int i = start; i < end; i++) sum += g_deg[i];
    s[tid] = sum;
    __syncthreads();
    for (int off = 1; off < 1024; off <<= 1) {
        int v = (tid >= off) ? s[tid - off] : 0;
        __syncthreads();
        s[tid] += v;
        __syncthreads();
    }
    int base = (tid == 0) ? 0 : s[tid - 1];
    for (int i = start; i < end; i++) { g_rowptr[i] = base; base += g_deg[i]; }
    if (tid == 1023) g_rowptr[n] = base;
}

__global__ void k_fill(const int* __restrict__ src, const int* __restrict__ dst, int e) {
    int i = blockIdx.x * blockDim.x + threadIdx.x;
    if (i < e) {
        int d = dst[i];
        int pos = atomicAdd(&g_cursor[d], 1);
        g_csr[g_rowptr[d] + pos] = src[i];
    }
}

// ---------------- aggregation, layer 1 (F=16, raw x, no BN) ----------------
__global__ void k_agg16(const float* __restrict__ x, const float* __restrict__ eps_p, int n) {
    int gid = blockIdx.x * blockDim.x + threadIdx.x;
    int node = gid >> 4;
    int lane = gid & 15;
    if (node >= n) return;
    float eps1 = 1.0f + __ldg(eps_p);
    float acc = eps1 * __ldg(&x[(size_t)node * 16 + lane]);
    int s = g_rowptr[node], e = g_rowptr[node + 1];
    int i = s;
    for (; i + 4 <= e; i += 4) {
        int s0 = g_csr[i], s1 = g_csr[i + 1], s2 = g_csr[i + 2], s3 = g_csr[i + 3];
        acc += __ldg(&x[(size_t)s0 * 16 + lane]) + __ldg(&x[(size_t)s1 * 16 + lane]) +
               __ldg(&x[(size_t)s2 * 16 + lane]) + __ldg(&x[(size_t)s3 * 16 + lane]);
    }
    for (; i < e; i++) acc += __ldg(&x[(size_t)g_csr[i] * 16 + lane]);
    g_z[(size_t)node * 16 + lane] = acc;
}

// ---------------- aggregation H=128 with fused BN affine ----------------
// z = s .* [ (1+eps)*u_self + sum u_nb ] + (1+eps+deg) * t,  s=gamma*rinv, t=beta-s*mean
__global__ void k_agg128(const float* __restrict__ u, const __half* __restrict__ uh,
                         const float* __restrict__ gamma, const float* __restrict__ beta,
                         const float* __restrict__ bn, const float* __restrict__ eps_p,
                         float inv_n, int n) {
    int warp = (blockIdx.x * blockDim.x + threadIdx.x) >> 5;
    int lane = threadIdx.x & 31;
    if (warp >= n) return;
    int f0 = lane * 4;
    float4 ga = *(const float4*)&gamma[f0];
    float4 be = *(const float4*)&beta[f0];
    float m0 = bn[f0 + 0] * inv_n, m1 = bn[f0 + 1] * inv_n;
    float m2 = bn[f0 + 2] * inv_n, m3 = bn[f0 + 3] * inv_n;
    float r0 = rsqrtf(bn[128 + f0 + 0] * inv_n - m0 * m0 + BN_EPS);
    float r1 = rsqrtf(bn[128 + f0 + 1] * inv_n - m1 * m1 + BN_EPS);
    float r2 = rsqrtf(bn[128 + f0 + 2] * inv_n - m2 * m2 + BN_EPS);
    float r3 = rsqrtf(bn[128 + f0 + 3] * inv_n - m3 * m3 + BN_EPS);
    float s0 = ga.x * r0, t0 = be.x - s0 * m0;
    float s1 = ga.y * r1, t1 = be.y - s1 * m1;
    float s2 = ga.z * r2, t2 = be.z - s2 * m2;
    float s3 = ga.w * r3, t3 = be.w - s3 * m3;

    float eps1 = 1.0f + __ldg(eps_p);
    float4 self = ((const float4*)u)[(size_t)warp * 32 + lane];
    float ax = 0.f, ay = 0.f, az = 0.f, aw = 0.f;

    int sidx = g_rowptr[warp], eidx = g_rowptr[warp + 1];
    const uint2* uh2 = (const uint2*)uh;   // 4 halves per uint2
    int i = sidx;
    for (; i + 4 <= eidx; i += 4) {
        int n0 = g_csr[i], n1 = g_csr[i + 1], n2 = g_csr[i + 2], n3 = g_csr[i + 3];
        uint2 v0 = uh2[(size_t)n0 * 32 + lane];
        uint2 v1 = uh2[(size_t)n1 * 32 + lane];
        uint2 v2 = uh2[(size_t)n2 * 32 + lane];
        uint2 v3 = uh2[(size_t)n3 * 32 + lane];
        float2 a01 = __half22float2(*(__half2*)&v0.x), a23 = __half22float2(*(__half2*)&v0.y);
        float2 b01 = __half22float2(*(__half2*)&v1.x), b23 = __half22float2(*(__half2*)&v1.y);
        float2 c01 = __half22float2(*(__half2*)&v2.x), c23 = __half22float2(*(__half2*)&v2.y);
        float2 d01 = __half22float2(*(__half2*)&v3.x), d23 = __half22float2(*(__half2*)&v3.y);
        ax += a01.x + b01.x + c01.x + d01.x;
        ay += a01.y + b01.y + c01.y + d01.y;
        az += a23.x + b23.x + c23.x + d23.x;
        aw += a23.y + b23.y + c23.y + d23.y;
    }
    for (; i < eidx; i++) {
        uint2 v = uh2[(size_t)g_csr[i] * 32 + lane];
        float2 p = __half22float2(*(__half2*)&v.x), q = __half22float2(*(__half2*)&v.y);
        ax += p.x; ay += p.y; az += q.x; aw += q.y;
    }
    float deg = (float)(eidx - sidx);
    float tc = eps1 + deg;
    float4 res;
    res.x = s0 * (eps1 * self.x + ax) + tc * t0;
    res.y = s1 * (eps1 * self.y + ay) + tc * t1;
    res.z = s2 * (eps1 * self.z + az) + tc * t2;
    res.w = s3 * (eps1 * self.w + aw) + tc * t3;
    ((float4*)g_z)[(size_t)warp * 32 + lane] = res;
}

// ---------------- SGEMM: C = relu(A @ W + b), optional fp16 mirror + BN stats ----------------
__global__ void __launch_bounds__(256, 2)
k_gemm_relu(const float* __restrict__ A, const float* __restrict__ W,
            const float* __restrict__ bias, float* __restrict__ C,
            __half* __restrict__ Ch, float* __restrict__ bnslot, int n, int K) {
    __shared__ float As[2][16][128];
    __shared__ float Ws[2][16][128];
    int row0 = blockIdx.x * 128;
    int tid = threadIdx.x;
    int tcol = tid & 15, trow = tid >> 4;
    int li1 = tid + 256;
    int am0 = tid >> 2, ak0 = (tid & 3) * 4;
    int am1 = li1 >> 2, ak1 = (li1 & 3) * 4;
    int wk0 = tid >> 5, wc0 = (tid & 31) * 4;
    int wk1 = li1 >> 5, wc1 = (li1 & 31) * 4;
    int ntiles = K >> 4;
    int gr0 = row0 + am0, gr1 = row0 + am1;

    float4 a0r, a1r, w0r, w1r;
    a0r = (gr0 < n) ? *(const float4*)&A[(size_t)gr0 * K + ak0] : make_float4(0, 0, 0, 0);
    a1r = (gr1 < n) ? *(const float4*)&A[(size_t)gr1 * K + ak1] : make_float4(0, 0, 0, 0);
    w0r = *(const float4*)&W[(size_t)wk0 * 128 + wc0];
    w1r = *(const float4*)&W[(size_t)wk1 * 128 + wc1];

    float acc[8][8];
#pragma unroll
    for (int i = 0; i < 8; i++)
#pragma unroll
        for (int j = 0; j < 8; j++) acc[i][j] = 0.0f;

    int buf = 0;
    for (int kt = 0; kt < ntiles; kt++) {
        As[buf][ak0 + 0][am0] = a0r.x; As[buf][ak0 + 1][am0] = a0r.y;
        As[buf][ak0 + 2][am0] = a0r.z; As[buf][ak0 + 3][am0] = a0r.w;
        As[buf][ak1 + 0][am1] = a1r.x; As[buf][ak1 + 1][am1] = a1r.y;
        As[buf][ak1 + 2][am1] = a1r.z; As[buf][ak1 + 3][am1] = a1r.w;
        *(float4*)&Ws[buf][wk0][wc0] = w0r;
        *(float4*)&Ws[buf][wk1][wc1] = w1r;
        __syncthreads();
        if (kt + 1 < ntiles) {
            int kb = (kt + 1) * 16;
            a0r = (gr0 < n) ? *(const float4*)&A[(size_t)gr0 * K + kb + ak0] : make_float4(0, 0, 0, 0);
            a1r = (gr1 < n) ? *(const float4*)&A[(size_t)gr1 * K + kb + ak1] : make_float4(0, 0, 0, 0);
            w0r = *(const float4*)&W[(size_t)(kb + wk0) * 128 + wc0];
            w1r = *(const float4*)&W[(size_t)(kb + wk1) * 128 + wc1];
        }
#pragma unroll
        for (int bk = 0; bk < 16; bk++) {
            float a[8], w[8];
            float4 aa0 = *(float4*)&As[buf][bk][trow * 8];
            float4 aa1 = *(float4*)&As[buf][bk][trow * 8 + 4];
            float4 ww0 = *(float4*)&Ws[buf][bk][tcol * 8];
            float4 ww1 = *(float4*)&Ws[buf][bk][tcol * 8 + 4];
            a[0] = aa0.x; a[1] = aa0.y; a[2] = aa0.z; a[3] = aa0.w;
            a[4] = aa1.x; a[5] = aa1.y; a[6] = aa1.z; a[7] = aa1.w;
            w[0] = ww0.x; w[1] = ww0.y; w[2] = ww0.z; w[3] = ww0.w;
            w[4] = ww1.x; w[5] = ww1.y; w[6] = ww1.z; w[7] = ww1.w;
#pragma unroll
            for (int i = 0; i < 8; i++)
#pragma unroll
                for (int j = 0; j < 8; j++) acc[i][j] += a[i] * w[j];
        }
        buf ^= 1;
    }

    float bj[8];
#pragma unroll
    for (int j = 0; j < 8; j++) bj[j] = bias[tcol * 8 + j];
#pragma unroll
    for (int i = 0; i < 8; i++)
#pragma unroll
        for (int j = 0; j < 8; j++) acc[i][j] = fmaxf(acc[i][j] + bj[j], 0.0f);

#pragma unroll
    for (int i = 0; i < 8; i++) {
        int gr = row0 + trow * 8 + i;
        if (gr < n) {
            float4 o0 = make_float4(acc[i][0], acc[i][1], acc[i][2], acc[i][3]);
            float4 o1 = make_float4(acc[i][4], acc[i][5], acc[i][6], acc[i][7]);
            *(float4*)&C[(size_t)gr * 128 + tcol * 8] = o0;
            *(float4*)&C[(size_t)gr * 128 + tcol * 8 + 4] = o1;
            if (Ch) {
                __half2* hrow = (__half2*)(Ch) + (size_t)gr * 64 + tcol * 4;
                hrow[0] = __floats2half2_rn(acc[i][0], acc[i][1]);
                hrow[1] = __floats2half2_rn(acc[i][2], acc[i][3]);
                hrow[2] = __floats2half2_rn(acc[i][4], acc[i][5]);
                hrow[3] = __floats2half2_rn(acc[i][6], acc[i][7]);
            }
        }
    }

    if (bnslot) {
        __syncthreads();
        float* sbn = &As[0][0][0];   // reuse smem: 256 floats
        sbn[tid] = 0.0f;
        __syncthreads();
        int nvalid = min(max(n - (row0 + trow * 8), 0), 8);
#pragma unroll
        for (int j = 0; j < 8; j++) {
            float s = 0.f, s2 = 0.f;
            for (int i = 0; i < nvalid; i++) { float v = acc[i][j]; s += v; s2 += v * v; }
            atomicAdd(&sbn[tcol * 8 + j], s);
            atomicAdd(&sbn[128 + tcol * 8 + j], s2);
        }
        __syncthreads();
        atomicAdd(&bnslot[tid], sbn[tid]);
    }
}

// ---------------- per-graph mean pool of RAW embeddings (batch sorted) ----------------
__global__ void k_pool(const int* __restrict__ batch, int n) {
    int f = threadIdx.x;            // 0..511 ; feature = slab*128 + col
    int slab = f >> 7, col = f & 127;
    int chunk = (n + gridDim.x - 1) / gridDim.x;
    int start = blockIdx.x * chunk;
    int end = min(start + chunk, n);
    if (start >= end) return;
    const float* base = g_emb + (size_t)slab * NMAX * HDIM;
    float acc = 0.f;
    int cnt = 0;
    int cur = batch[start];
    for (int i = start; i < end; i++) {
        int g = batch[i];
        if (g != cur) {
            atomicAdd(&g_pool[cur * 512 + f], acc);
            if (f == 0) atomicAdd(&g_cnt[cur], (float)cnt);
            acc = 0.f; cnt = 0; cur = g;
        }
        acc += base[(size_t)i * 128 + col];
        cnt++;
    }
    atomicAdd(&g_pool[cur * 512 + f], acc);
    if (f == 0) atomicAdd(&g_cnt[cur], (float)cnt);
}

// ---------------- classifier with BN affine on pooled means ----------------
__global__ void k_classifier(const float* __restrict__ W1, const float* __restrict__ b1,
                             const float* __restrict__ W2, const float* __restrict__ b2,
                             const float* __restrict__ W3, const float* __restrict__ b3,
                             const float* __restrict__ W4, const float* __restrict__ b4,
                             const float* __restrict__ c1g, const float* __restrict__ c1b,
                             const float* __restrict__ cg, const float* __restrict__ cb,
                             float inv_n, float* __restrict__ out) {
    __shared__ float emb[512], h1[256], h2[128], h3[128], logits[10];
    int g = blockIdx.x;
    int tid = threadIdx.x;   // 256 threads
    float cnt = fmaxf(g_cnt[g], 1.0f);
    for (int f = tid; f < 512; f += 256) {
        int slab = f >> 7, col = f & 127;
        const float* G = (slab == 0) ? c1g : cg + (slab - 1) * 128;
        const float* B = (slab == 0) ? c1b : cb + (slab - 1) * 128;
        float m = g_bn[slab * 256 + col] * inv_n;
        float r = rsqrtf(g_bn[slab * 256 + 128 + col] * inv_n - m * m + BN_EPS);
        float s = G[col] * r;
        float t = B[col] - s * m;
        emb[f] = s * (g_pool[g * 512 + f] / cnt) + t;
    }
    __syncthreads();
    {
        float a = b1[tid];
        for (int k = 0; k < 512; k++) a += emb[k] * W1[k * 256 + tid];
        h1[tid] = fmaxf(a, 0.f);
    }
    __syncthreads();
    if (tid < 128) {
        float a = b2[tid];
        for (int k = 0; k < 256; k++) a += h1[k] * W2[k * 128 + tid];
        h2[tid] = fmaxf(a, 0.f);
    }
    __syncthreads();
    if (tid < 128) {
        float a = b3[tid];
        for (int k = 0; k < 128; k++) a += h2[k] * W3[k * 128 + tid];
        h3[tid] = fmaxf(a, 0.f);
    }
    __syncthreads();
    if (tid < 10) {
        float a = b4[tid];
        for (int k = 0; k < 128; k++) a += h3[k] * W4[k * 10 + tid];
        logits[tid] = a;
    }
    __syncthreads();
    if (tid == 0) {
        float mx = logits[0];
        for (int c = 1; c < 10; c++) mx = fmaxf(mx, logits[c]);
        float se = 0.f;
        for (int c = 0; c < 10; c++) se += expf(logits[c] - mx);
        float lse = logf(se) + mx;
        for (int c = 0; c < 10; c++) out[g * 10 + c] = logits[c] - lse;
    }
}

// ---------------- launch orchestration ----------------
extern "C" void kernel_launch(void* const* d_in, const int* in_sizes, int n_in,
                              void* d_out, int out_size) {
    const float* x     = (const float*)d_in[0];
    const int*   ei    = (const int*)d_in[1];
    const int*   batch = (const int*)d_in[2];
    const float* c1W1 = (const float*)d_in[3];
    const float* c1b1 = (const float*)d_in[4];
    const float* c1W2 = (const float*)d_in[5];
    const float* c1b2 = (const float*)d_in[6];
    const float* c1g  = (const float*)d_in[7];
    const float* c1b  = (const float*)d_in[8];
    const float* c1e  = (const float*)d_in[9];
    const float* cW1  = (const float*)d_in[10];
    const float* cb1  = (const float*)d_in[11];
    const float* cW2  = (const float*)d_in[12];
    const float* cb2  = (const float*)d_in[13];
    const float* cg   = (const float*)d_in[14];
    const float* cb   = (const float*)d_in[15];
    const float* ce   = (const float*)d_in[16];
    const float* lW1 = (const float*)d_in[17];
    const float* lb1 = (const float*)d_in[18];
    const float* lW2 = (const float*)d_in[19];
    const float* lb2 = (const float*)d_in[20];
    const float* lW3 = (const float*)d_in[21];
    const float* lb3 = (const float*)d_in[22];
    const float* lW4 = (const float*)d_in[23];
    const float* lb4 = (const float*)d_in[24];
    float* out = (float*)d_out;

    int n = in_sizes[0] / 16;
    int e = in_sizes[1] / 2;
    if (n > NMAX) n = NMAX;
    if (e > EMAX) e = EMAX;
    const int* src = ei;
    const int* dst = ei + e;
    float inv_n = 1.0f / (float)n;

    float*  z_ptr;    cudaGetSymbolAddress((void**)&z_ptr, g_z);
    float*  t_ptr;    cudaGetSymbolAddress((void**)&t_ptr, g_t);
    float*  emb_ptr;  cudaGetSymbolAddress((void**)&emb_ptr, g_emb);
    __half* embh_ptr; cudaGetSymbolAddress((void**)&embh_ptr, g_embh);
    float*  bn_ptr;   cudaGetSymbolAddress((void**)&bn_ptr, g_bn);

    k_zero<<<256, 256>>>(n);
    k_count<<<(e + 255) / 256, 256>>>(dst, e);
    k_scan<<<1, 1024>>>(n);
    k_fill<<<(e + 255) / 256, 256>>>(src, dst, e);

    int gemm_blocks = (n + 127) / 128;

    // Layer 1 (F=16 input)
    k_agg16<<<(n * 16 + 255) / 256, 256>>>(x, c1e, n);
    k_gemm_relu<<<gemm_blocks, 256>>>(z_ptr, c1W1, c1b1, t_ptr,
                                      (__half*)nullptr, (float*)nullptr, n, 16);
    k_gemm_relu<<<gemm_blocks, 256>>>(t_ptr, c1W2, c1b2, emb_ptr, embh_ptr, bn_ptr, n, 128);

    // Layers 2-4
    for (int l = 1; l < 4; l++) {
        int i = l - 1;
        const float* gprev = (l == 1) ? c1g : cg + (l - 2) * 128;
        const float* bprev = (l == 1) ? c1b : cb + (l - 2) * 128;
        k_agg128<<<(n * 32 + 255) / 256, 256>>>(
            emb_ptr + (size_t)(l - 1) * NMAX * HDIM,
            embh_ptr + (size_t)(l - 1) * NMAX * HDIM,
            gprev, bprev, bn_ptr + (l - 1) * 256, ce + i, inv_n, n);
        k_gemm_relu<<<gemm_blocks, 256>>>(z_ptr, cW1 + (size_t)i * 128 * 128, cb1 + i * 128,
                                          t_ptr, (__half*)nullptr, (float*)nullptr, n, 128);
        k_gemm_relu<<<gemm_blocks, 256>>>(t_ptr, cW2 + (size_t)i * 128 * 128, cb2 + i * 128,
                                          emb_ptr + (size_t)l * NMAX * HDIM,
                                          embh_ptr + (size_t)l * NMAX * HDIM,
                                          bn_ptr + l * 256, n, 128);
    }

    k_pool<<<200, 512>>>(batch, n);
    k_classifier<<<NGRAPH, 256>>>(lW1, lb1, lW2, lb2, lW3, lb3, lW4, lb4,
                                  c1g, c1b, cg, cb, inv_n, out);
}

// round 4
// speedup vs baseline: 1.9075x; 1.6228x over previous
#include <cuda_runtime.h>
#include <cuda_fp16.h>
#include <mma.h>
#include <math.h>

using namespace nvcuda;

#define NMAX 100000
#define EMAX 1600000
#define HDIM 128
#define NGRAPH 64
#define BN_EPS 1e-5f

// ---------------- static device scratch ----------------
__device__ __half g_embh[4ll * NMAX * HDIM];   // fp16 layer outputs (pre-BN)
__device__ __half g_zh[(size_t)NMAX * HDIM];   // aggregation output (gemm A)
__device__ __half g_th[(size_t)NMAX * HDIM];   // mlp intermediate (gemm A)
__device__ __half g_wh[8 * 16384];             // fp16 weights: slot*16384
__device__ int    g_deg[NMAX];
__device__ int    g_cursor[NMAX];
__device__ int    g_rowptr[NMAX + 1];
__device__ int    g_csr[EMAX];
__device__ float  g_bn[4 * 256];               // per layer: [0..127]=sum, [128..255]=sumsq
__device__ float  g_pool[NGRAPH * 512];
__device__ float  g_cnt[NGRAPH];

// ---------------- zero ----------------
__global__ void k_zero(int n) {
    int i = blockIdx.x * blockDim.x + threadIdx.x;
    int stride = gridDim.x * blockDim.x;
    for (int j = i; j < n; j += stride) { g_deg[j] = 0; g_cursor[j] = 0; }
    for (int j = i; j < 4 * 256; j += stride) g_bn[j] = 0.0f;
    for (int j = i; j < NGRAPH * 512; j += stride) g_pool[j] = 0.0f;
    for (int j = i; j < NGRAPH; j += stride) g_cnt[j] = 0.0f;
}

// ---------------- weight conversion to fp16 ----------------
// slot 0: c1W1 (16x128, rest zero); slot 1: c1W2; slot 2+2i: convs_W1[i]; slot 3+2i: convs_W2[i]
__global__ void k_wconv(const float* __restrict__ c1W1, const float* __restrict__ c1W2,
                        const float* __restrict__ cW1, const float* __restrict__ cW2) {
    int idx = blockIdx.x * blockDim.x + threadIdx.x;
    if (idx >= 8 * 16384) return;
    int slot = idx >> 14;
    int off = idx & 16383;
    float v = 0.0f;
    if (slot == 0) { if (off < 2048) v = c1W1[off]; }
    else if (slot == 1) v = c1W2[off];
    else {
        int i = (slot - 2) >> 1;
        v = (slot & 1) ? cW2[i * 16384 + off] : cW1[i * 16384 + off];
    }
    g_wh[idx] = __float2half(v);
}

// ---------------- CSR build ----------------
__global__ void k_count(const int* __restrict__ dst, int e) {
    int i = blockIdx.x * blockDim.x + threadIdx.x;
    if (i < e) atomicAdd(&g_deg[dst[i]], 1);
}

__global__ void k_scan(int n) {
    __shared__ int s[1024];
    int tid = threadIdx.x;
    int chunk = (n + 1023) / 1024;
    int start = tid * chunk;
    int end = min(start + chunk, n);
    int sum = 0;
    for (int i = start; i < end; i++) sum += g_deg[i];
    s[tid] = sum;
    __syncthreads();
    for (int off = 1; off < 1024; off <<= 1) {
        int v = (tid >= off) ? s[tid - off] : 0;
        __syncthreads();
        s[tid] += v;
        __syncthreads();
    }
    int base = (tid == 0) ? 0 : s[tid - 1];
    for (int i = start; i < end; i++) { g_rowptr[i] = base; base += g_deg[i]; }
    if (tid == 1023) g_rowptr[n] = base;
}

__global__ void k_fill(const int* __restrict__ src, const int* __restrict__ dst, int e) {
    int i = blockIdx.x * blockDim.x + threadIdx.x;
    if (i < e) {
        int d = dst[i];
        int pos = atomicAdd(&g_cursor[d], 1);
        g_csr[g_rowptr[d] + pos] = src[i];
    }
}

// ---------------- aggregation, layer 1 (F=16, raw x) -> fp16 z ----------------
__global__ void k_agg16(const float* __restrict__ x, const float* __restrict__ eps_p, int n) {
    int gid = blockIdx.x * blockDim.x + threadIdx.x;
    int node = gid >> 4;
    int lane = gid & 15;
    if (node >= n) return;
    float eps1 = 1.0f + __ldg(eps_p);
    float acc = eps1 * __ldg(&x[(size_t)node * 16 + lane]);
    int s = g_rowptr[node], e = g_rowptr[node + 1];
    int i = s;
    for (; i + 4 <= e; i += 4) {
        int s0 = g_csr[i], s1 = g_csr[i + 1], s2 = g_csr[i + 2], s3 = g_csr[i + 3];
        acc += __ldg(&x[(size_t)s0 * 16 + lane]) + __ldg(&x[(size_t)s1 * 16 + lane]) +
               __ldg(&x[(size_t)s2 * 16 + lane]) + __ldg(&x[(size_t)s3 * 16 + lane]);
    }
    for (; i < e; i++) acc += __ldg(&x[(size_t)g_csr[i] * 16 + lane]);
    g_zh[(size_t)node * 16 + lane] = __float2half(acc);
}

// ---------------- aggregation H=128 (fp16 in/out) with fused BN affine ----------------
// z = s .* [ (1+eps)*u_self + sum u_nb ] + (1+eps+deg) * t,  s=gamma*rinv, t=beta-s*mean
__global__ void k_agg128(const __half* __restrict__ uh,
                         const float* __restrict__ gamma, const float* __restrict__ beta,
                         const float* __restrict__ bn, const float* __restrict__ eps_p,
                         float inv_n, int n) {
    int warp = (blockIdx.x * blockDim.x + threadIdx.x) >> 5;
    int lane = threadIdx.x & 31;
    if (warp >= n) return;
    int f0 = lane * 4;
    float4 ga = *(const float4*)&gamma[f0];
    float4 be = *(const float4*)&beta[f0];
    float m0 = bn[f0 + 0] * inv_n, m1 = bn[f0 + 1] * inv_n;
    float m2 = bn[f0 + 2] * inv_n, m3 = bn[f0 + 3] * inv_n;
    float r0 = rsqrtf(bn[128 + f0 + 0] * inv_n - m0 * m0 + BN_EPS);
    float r1 = rsqrtf(bn[128 + f0 + 1] * inv_n - m1 * m1 + BN_EPS);
    float r2 = rsqrtf(bn[128 + f0 + 2] * inv_n - m2 * m2 + BN_EPS);
    float r3 = rsqrtf(bn[128 + f0 + 3] * inv_n - m3 * m3 + BN_EPS);
    float s0 = ga.x * r0, t0 = be.x - s0 * m0;
    float s1 = ga.y * r1, t1 = be.y - s1 * m1;
    float s2 = ga.z * r2, t2 = be.z - s2 * m2;
    float s3 = ga.w * r3, t3 = be.w - s3 * m3;

    float eps1 = 1.0f + __ldg(eps_p);
    const uint2* uh2 = (const uint2*)uh;   // 4 halves per uint2
    uint2 sv = uh2[(size_t)warp * 32 + lane];
    float2 sp = __half22float2(*(__half2*)&sv.x), sq = __half22float2(*(__half2*)&sv.y);
    float ax = 0.f, ay = 0.f, az = 0.f, aw = 0.f;

    int sidx = g_rowptr[warp], eidx = g_rowptr[warp + 1];
    int i = sidx;
    for (; i + 4 <= eidx; i += 4) {
        int n0 = g_csr[i], n1 = g_csr[i + 1], n2 = g_csr[i + 2], n3 = g_csr[i + 3];
        uint2 v0 = uh2[(size_t)n0 * 32 + lane];
        uint2 v1 = uh2[(size_t)n1 * 32 + lane];
        uint2 v2 = uh2[(size_t)n2 * 32 + lane];
        uint2 v3 = uh2[(size_t)n3 * 32 + lane];
        float2 a01 = __half22float2(*(__half2*)&v0.x), a23 = __half22float2(*(__half2*)&v0.y);
        float2 b01 = __half22float2(*(__half2*)&v1.x), b23 = __half22float2(*(__half2*)&v1.y);
        float2 c01 = __half22float2(*(__half2*)&v2.x), c23 = __half22float2(*(__half2*)&v2.y);
        float2 d01 = __half22float2(*(__half2*)&v3.x), d23 = __half22float2(*(__half2*)&v3.y);
        ax += a01.x + b01.x + c01.x + d01.x;
        ay += a01.y + b01.y + c01.y + d01.y;
        az += a23.x + b23.x + c23.x + d23.x;
        aw += a23.y + b23.y + c23.y + d23.y;
    }
    for (; i < eidx; i++) {
        uint2 v = uh2[(size_t)g_csr[i] * 32 + lane];
        float2 p = __half22float2(*(__half2*)&v.x), q = __half22float2(*(__half2*)&v.y);
        ax += p.x; ay += p.y; az += q.x; aw += q.y;
    }
    float deg = (float)(eidx - sidx);
    float tc = eps1 + deg;
    float rx = s0 * (eps1 * sp.x + ax) + tc * t0;
    float ry = s1 * (eps1 * sp.y + ay) + tc * t1;
    float rz = s2 * (eps1 * sq.x + az) + tc * t2;
    float rw = s3 * (eps1 * sq.y + aw) + tc * t3;
    uint2 outv;
    *(__half2*)&outv.x = __floats2half2_rn(rx, ry);
    *(__half2*)&outv.y = __floats2half2_rn(rz, rw);
    ((uint2*)g_zh)[(size_t)warp * 32 + lane] = outv;
}

// ---------------- Tensor-core GEMM: C(fp16) = relu(A(fp16)[n x K] @ W(fp16)[K x 128] + b) ----------------
// BM=128, BN=128, BK=32, 256 threads (8 warps, 2x4), warp tile 64x32 via wmma 16x16x16
__global__ void __launch_bounds__(256)
k_gemm_tc(const __half* __restrict__ A, const __half* __restrict__ W,
          const float* __restrict__ bias, __half* __restrict__ Ch,
          float* __restrict__ bnslot, int n, int K) {
    __shared__ __half As[128][40];
    __shared__ __half Bs[32][136];
    __shared__ float Cbuf[32][132];
    __shared__ float sbn[256];

    int tid = threadIdx.x;
    int wid = tid >> 5;
    int warp_row = wid >> 2;       // 0..1 (64-row groups)
    int warp_col = wid & 3;        // 0..3 (32-col groups)
    int row0 = blockIdx.x * 128;

    wmma::fragment<wmma::accumulator, 16, 16, 16, float> acc[4][2];
#pragma unroll
    for (int r = 0; r < 4; r++)
#pragma unroll
        for (int c = 0; c < 2; c++) wmma::fill_fragment(acc[r][c], 0.0f);

    for (int kb = 0; kb < K; kb += 32) {
        // load A tile: 128 rows x 32 cols (halves); 512 uint4 loads
#pragma unroll
        for (int l = 0; l < 2; l++) {
            int idx = tid + l * 256;
            int row = idx >> 2;
            int col = (idx & 3) * 8;
            int gr = row0 + row;
            uint4 v = make_uint4(0, 0, 0, 0);
            if (gr < n && (kb + col) < K)
                v = *(const uint4*)&A[(size_t)gr * K + kb + col];
            *(uint4*)&As[row][col] = v;
        }
        // load B tile: 32 rows x 128 cols
#pragma unroll
        for (int l = 0; l < 2; l++) {
            int idx = tid + l * 256;
            int krow = idx >> 4;
            int col = (idx & 15) * 8;
            uint4 v = make_uint4(0, 0, 0, 0);
            if ((kb + krow) < K)
                v = *(const uint4*)&W[(size_t)(kb + krow) * 128 + col];
            *(uint4*)&Bs[krow][col] = v;
        }
        __syncthreads();
#pragma unroll
        for (int kk = 0; kk < 32; kk += 16) {
            wmma::fragment<wmma::matrix_a, 16, 16, 16, __half, wmma::row_major> af[4];
            wmma::fragment<wmma::matrix_b, 16, 16, 16, __half, wmma::row_major> bf[2];
#pragma unroll
            for (int r = 0; r < 4; r++)
                wmma::load_matrix_sync(af[r], &As[warp_row * 64 + r * 16][kk], 40);
#pragma unroll
            for (int c = 0; c < 2; c++)
                wmma::load_matrix_sync(bf[c], &Bs[kk][warp_col * 32 + c * 16], 136);
#pragma unroll
            for (int r = 0; r < 4; r++)
#pragma unroll
                for (int c = 0; c < 2; c++)
                    wmma::mma_sync(acc[r][c], af[r], bf[c], acc[r][c]);
        }
        __syncthreads();
    }

    // epilogue: 4 waves of 32 rows each through Cbuf
    int erow = tid >> 4;           // 0..15
    int ecg = tid & 15;            // col group of 8
    float bj[8];
#pragma unroll
    for (int j = 0; j < 8; j++) bj[j] = bias[ecg * 8 + j];
    float bs[8], bq[8];
#pragma unroll
    for (int j = 0; j < 8; j++) { bs[j] = 0.f; bq[j] = 0.f; }

    for (int v = 0; v < 4; v++) {
        if (warp_row == (v >> 1)) {
#pragma unroll
            for (int t = 0; t < 2; t++) {
                int fr = (v & 1) * 2 + t;
#pragma unroll
                for (int c = 0; c < 2; c++)
                    wmma::store_matrix_sync(&Cbuf[t * 16][warp_col * 32 + c * 16],
                                            acc[fr][c], 132, wmma::mem_row_major);
            }
        }
        __syncthreads();
#pragma unroll
        for (int it = 0; it < 2; it++) {
            int rw = erow + it * 16;
            int gr = row0 + v * 32 + rw;
            if (gr < n) {
                float vals[8];
#pragma unroll
                for (int j = 0; j < 8; j++) {
                    float z = fmaxf(Cbuf[rw][ecg * 8 + j] + bj[j], 0.0f);
                    vals[j] = z;
                    bs[j] += z;
                    bq[j] += z * z;
                }
                uint4 h;
                *(__half2*)&h.x = __floats2half2_rn(vals[0], vals[1]);
                *(__half2*)&h.y = __floats2half2_rn(vals[2], vals[3]);
                *(__half2*)&h.z = __floats2half2_rn(vals[4], vals[5]);
                *(__half2*)&h.w = __floats2half2_rn(vals[6], vals[7]);
                *(uint4*)&Ch[(size_t)gr * 128 + ecg * 8] = h;
            }
        }
        __syncthreads();
    }

    if (bnslot) {
        sbn[tid] = 0.0f;
        __syncthreads();
#pragma unroll
        for (int j = 0; j < 8; j++) {
            atomicAdd(&sbn[ecg * 8 + j], bs[j]);
            atomicAdd(&sbn[128 + ecg * 8 + j], bq[j]);
        }
        __syncthreads();
        atomicAdd(&bnslot[tid], sbn[tid]);
    }
}

// ---------------- per-graph mean pool of fp16 embeddings (batch sorted) ----------------
__global__ void k_pool(const int* __restrict__ batch, int n) {
    int f = threadIdx.x;            // 0..511 ; feature = slab*128 + col
    int slab = f >> 7, col = f & 127;
    int chunk = (n + gridDim.x - 1) / gridDim.x;
    int start = blockIdx.x * chunk;
    int end = min(start + chunk, n);
    if (start >= end) return;
    const __half* base = g_embh + (size_t)slab * NMAX * HDIM;
    float acc = 0.f;
    int cnt = 0;
    int cur = batch[start];
    for (int i = start; i < end; i++) {
        int g = batch[i];
        if (g != cur) {
            atomicAdd(&g_pool[cur * 512 + f], acc);
            if (f == 0) atomicAdd(&g_cnt[cur], (float)cnt);
            acc = 0.f; cnt = 0; cur = g;
        }
        acc += __half2float(base[(size_t)i * 128 + col]);
        cnt++;
    }
    atomicAdd(&g_pool[cur * 512 + f], acc);
    if (f == 0) atomicAdd(&g_cnt[cur], (float)cnt);
}

// ---------------- classifier with BN affine on pooled means ----------------
__global__ void k_classifier(const float* __restrict__ W1, const float* __restrict__ b1,
                             const float* __restrict__ W2, const float* __restrict__ b2,
                             const float* __restrict__ W3, const float* __restrict__ b3,
                             const float* __restrict__ W4, const float* __restrict__ b4,
                             const float* __restrict__ c1g, const float* __restrict__ c1b,
                             const float* __restrict__ cg, const float* __restrict__ cb,
                             float inv_n, float* __restrict__ out) {
    __shared__ float emb[512], h1[256], h2[128], h3[128], logits[10];
    int g = blockIdx.x;
    int tid = threadIdx.x;   // 256 threads
    float cnt = fmaxf(g_cnt[g], 1.0f);
    for (int f = tid; f < 512; f += 256) {
        int slab = f >> 7, col = f & 127;
        const float* G = (slab == 0) ? c1g : cg + (slab - 1) * 128;
        const float* B = (slab == 0) ? c1b : cb + (slab - 1) * 128;
        float m = g_bn[slab * 256 + col] * inv_n;
        float r = rsqrtf(g_bn[slab * 256 + 128 + col] * inv_n - m * m + BN_EPS);
        float s = G[col] * r;
        float t = B[col] - s * m;
        emb[f] = s * (g_pool[g * 512 + f] / cnt) + t;
    }
    __syncthreads();
    {
        float a = b1[tid];
        for (int k = 0; k < 512; k++) a += emb[k] * W1[k * 256 + tid];
        h1[tid] = fmaxf(a, 0.f);
    }
    __syncthreads();
    if (tid < 128) {
        float a = b2[tid];
        for (int k = 0; k < 256; k++) a += h1[k] * W2[k * 128 + tid];
        h2[tid] = fmaxf(a, 0.f);
    }
    __syncthreads();
    if (tid < 128) {
        float a = b3[tid];
        for (int k = 0; k < 128; k++) a += h2[k] * W3[k * 128 + tid];
        h3[tid] = fmaxf(a, 0.f);
    }
    __syncthreads();
    if (tid < 10) {
        float a = b4[tid];
        for (int k = 0; k < 128; k++) a += h3[k] * W4[k * 10 + tid];
        logits[tid] = a;
    }
    __syncthreads();
    if (tid == 0) {
        float mx = logits[0];
        for (int c = 1; c < 10; c++) mx = fmaxf(mx, logits[c]);
        float se = 0.f;
        for (int c = 0; c < 10; c++) se += expf(logits[c] - mx);
        float lse = logf(se) + mx;
        for (int c = 0; c < 10; c++) out[g * 10 + c] = logits[c] - lse;
    }
}

// ---------------- launch orchestration ----------------
extern "C" void kernel_launch(void* const* d_in, const int* in_sizes, int n_in,
                              void* d_out, int out_size) {
    const float* x     = (const float*)d_in[0];
    const int*   ei    = (const int*)d_in[1];
    const int*   batch = (const int*)d_in[2];
    const float* c1W1 = (const float*)d_in[3];
    const float* c1b1 = (const float*)d_in[4];
    const float* c1W2 = (const float*)d_in[5];
    const float* c1b2 = (const float*)d_in[6];
    const float* c1g  = (const float*)d_in[7];
    const float* c1b  = (const float*)d_in[8];
    const float* c1e  = (const float*)d_in[9];
    const float* cW1  = (const float*)d_in[10];
    const float* cb1  = (const float*)d_in[11];
    const float* cW2  = (const float*)d_in[12];
    const float* cb2  = (const float*)d_in[13];
    const float* cg   = (const float*)d_in[14];
    const float* cb   = (const float*)d_in[15];
    const float* ce   = (const float*)d_in[16];
    const float* lW1 = (const float*)d_in[17];
    const float* lb1 = (const float*)d_in[18];
    const float* lW2 = (const float*)d_in[19];
    const float* lb2 = (const float*)d_in[20];
    const float* lW3 = (const float*)d_in[21];
    const float* lb3 = (const float*)d_in[22];
    const float* lW4 = (const float*)d_in[23];
    const float* lb4 = (const float*)d_in[24];
    float* out = (float*)d_out;

    int n = in_sizes[0] / 16;
    int e = in_sizes[1] / 2;
    if (n > NMAX) n = NMAX;
    if (e > EMAX) e = EMAX;
    const int* src = ei;
    const int* dst = ei + e;
    float inv_n = 1.0f / (float)n;

    __half* zh_ptr;   cudaGetSymbolAddress((void**)&zh_ptr, g_zh);
    __half* th_ptr;   cudaGetSymbolAddress((void**)&th_ptr, g_th);
    __half* embh_ptr; cudaGetSymbolAddress((void**)&embh_ptr, g_embh);
    __half* wh_ptr;   cudaGetSymbolAddress((void**)&wh_ptr, g_wh);
    float*  bn_ptr;   cudaGetSymbolAddress((void**)&bn_ptr, g_bn);

    k_zero<<<256, 256>>>(n);
    k_wconv<<<512, 256>>>(c1W1, c1W2, cW1, cW2);
    k_count<<<(e + 255) / 256, 256>>>(dst, e);
    k_scan<<<1, 1024>>>(n);
    k_fill<<<(e + 255) / 256, 256>>>(src, dst, e);

    int gemm_blocks = (n + 127) / 128;

    // Layer 1 (F=16 input)
    k_agg16<<<(n * 16 + 255) / 256, 256>>>(x, c1e, n);
    k_gemm_tc<<<gemm_blocks, 256>>>(zh_ptr, wh_ptr + 0 * 16384, c1b1, th_ptr,
                                    (float*)nullptr, n, 16);
    k_gemm_tc<<<gemm_blocks, 256>>>(th_ptr, wh_ptr + 1 * 16384, c1b2, embh_ptr,
                                    bn_ptr, n, 128);

    // Layers 2-4
    for (int l = 1; l < 4; l++) {
        int i = l - 1;
        const float* gprev = (l == 1) ? c1g : cg + (l - 2) * 128;
        const float* bprev = (l == 1) ? c1b : cb + (l - 2) * 128;
        k_agg128<<<(n * 32 + 255) / 256, 256>>>(
            embh_ptr + (size_t)(l - 1) * NMAX * HDIM,
            gprev, bprev, bn_ptr + (l - 1) * 256, ce + i, inv_n, n);
        k_gemm_tc<<<gemm_blocks, 256>>>(zh_ptr, wh_ptr + (2 + 2 * i) * 16384, cb1 + i * 128,
                                        th_ptr, (float*)nullptr, n, 128);
        k_gemm_tc<<<gemm_blocks, 256>>>(th_ptr, wh_ptr + (3 + 2 * i) * 16384, cb2 + i * 128,
                                        embh_ptr + (size_t)l * NMAX * HDIM,
                                        bn_ptr + l * 256, n, 128);
    }

    k_pool<<<200, 512>>>(batch, n);
    k_classifier<<<NGRAPH, 256>>>(lW1, lb1, lW2, lb2, lW3, lb3, lW4, lb4,
                                  c1g, c1b, cg, cb, inv_n, out);
}

// round 5
// speedup vs baseline: 2.1509x; 1.1276x over previous
#include <cuda_runtime.h>
#include <cuda_fp16.h>
#include <mma.h>
#include <math.h>

using namespace nvcuda;

#define NMAX 100000
#define EMAX 1600000
#define HDIM 128
#define NGRAPH 64
#define BN_EPS 1e-5f
#define SCAN_NB 240

// ---------------- static device scratch ----------------
__device__ __half g_embh[4ll * NMAX * HDIM];   // fp16 layer outputs (pre-BN)
__device__ __half g_zh[(size_t)NMAX * HDIM];   // aggregation output (gemm A)
__device__ __half g_th[(size_t)NMAX * HDIM];   // mlp intermediate (gemm A)
__device__ __half g_wh[8 * 16384];             // fp16 weights: slot*16384
__device__ int    g_deg[NMAX];
__device__ int    g_cursor[NMAX];
__device__ int    g_rowptr[NMAX + 1];
__device__ int    g_csr[EMAX];
__device__ int    g_bsum[SCAN_NB];
__device__ float  g_bn[4 * 256];               // per layer: [0..127]=sum, [128..255]=sumsq
__device__ float  g_pool[NGRAPH * 512];
__device__ float  g_cnt[NGRAPH];

// ---------------- zero ----------------
__global__ void k_zero(int n) {
    int i = blockIdx.x * blockDim.x + threadIdx.x;
    int stride = gridDim.x * blockDim.x;
    for (int j = i; j < n; j += stride) { g_deg[j] = 0; g_cursor[j] = 0; }
    for (int j = i; j < 4 * 256; j += stride) g_bn[j] = 0.0f;
    for (int j = i; j < NGRAPH * 512; j += stride) g_pool[j] = 0.0f;
    for (int j = i; j < NGRAPH; j += stride) g_cnt[j] = 0.0f;
}

// ---------------- weight conversion to fp16 ----------------
// slot 0: c1W1 (16x128, rest zero); slot 1: c1W2; slot 2+2i: convs_W1[i]; slot 3+2i: convs_W2[i]
__global__ void k_wconv(const float* __restrict__ c1W1, const float* __restrict__ c1W2,
                        const float* __restrict__ cW1, const float* __restrict__ cW2) {
    int idx = blockIdx.x * blockDim.x + threadIdx.x;
    if (idx >= 8 * 16384) return;
    int slot = idx >> 14;
    int off = idx & 16383;
    float v = 0.0f;
    if (slot == 0) { if (off < 2048) v = c1W1[off]; }
    else if (slot == 1) v = c1W2[off];
    else {
        int i = (slot - 2) >> 1;
        v = (slot & 1) ? cW2[i * 16384 + off] : cW1[i * 16384 + off];
    }
    g_wh[idx] = __float2half(v);
}

// ---------------- CSR build ----------------
__global__ void k_count(const int* __restrict__ dst, int e) {
    int i = blockIdx.x * blockDim.x + threadIdx.x;
    if (i < e) atomicAdd(&g_deg[dst[i]], 1);
}

// 3-phase parallel exclusive scan of g_deg -> g_rowptr
__global__ void k_scan1(int n, int chunk, int tch) {
    __shared__ int s[256];
    int tid = threadIdx.x;
    int bstart = blockIdx.x * chunk;
    int bend = min(bstart + chunk, n);
    int start = bstart + tid * tch;
    int end = min(start + tch, bend);
    int sum = 0;
    for (int i = start; i < end; i++) sum += g_deg[i];
    s[tid] = sum;
    __syncthreads();
    for (int off = 128; off > 0; off >>= 1) {
        if (tid < off) s[tid] += s[tid + off];
        __syncthreads();
    }
    if (tid == 0) g_bsum[blockIdx.x] = s[0];
}

__global__ void k_scan2(int n) {
    __shared__ int s[SCAN_NB];
    int tid = threadIdx.x;   // 256 >= SCAN_NB
    int v = (tid < SCAN_NB) ? g_bsum[tid] : 0;
    if (tid < SCAN_NB) s[tid] = v;
    __syncthreads();
    // serial-ish scan by thread 0 is fine for 240 entries? do Hillis-Steele
    for (int off = 1; off < SCAN_NB; off <<= 1) {
        int t = (tid < SCAN_NB && tid >= off) ? s[tid - off] : 0;
        __syncthreads();
        if (tid < SCAN_NB) s[tid] += t;
        __syncthreads();
    }
    if (tid < SCAN_NB) g_bsum[tid] = s[tid] - v;   // exclusive
    if (tid == SCAN_NB - 1) g_rowptr[n] = s[tid];  // total
}

__global__ void k_scan3(int n, int chunk, int tch) {
    __shared__ int s[256];
    int tid = threadIdx.x;
    int bstart = blockIdx.x * chunk;
    int bend = min(bstart + chunk, n);
    int start = bstart + tid * tch;
    int end = min(start + tch, bend);
    int sum = 0;
    for (int i = start; i < end; i++) sum += g_deg[i];
    s[tid] = sum;
    __syncthreads();
    for (int off = 1; off < 256; off <<= 1) {
        int t = (tid >= off) ? s[tid - off] : 0;
        __syncthreads();
        s[tid] += t;
        __syncthreads();
    }
    int base = g_bsum[blockIdx.x] + s[tid] - sum;   // exclusive within block + block base
    for (int i = start; i < end; i++) { g_rowptr[i] = base; base += g_deg[i]; }
}

__global__ void k_fill(const int* __restrict__ src, const int* __restrict__ dst, int e) {
    int i = blockIdx.x * blockDim.x + threadIdx.x;
    if (i < e) {
        int d = dst[i];
        int pos = atomicAdd(&g_cursor[d], 1);
        g_csr[g_rowptr[d] + pos] = src[i];
    }
}

// ---------------- aggregation, layer 1 (F=16, raw x) -> fp16 z ----------------
__global__ void k_agg16(const float* __restrict__ x, const float* __restrict__ eps_p, int n) {
    int gid = blockIdx.x * blockDim.x + threadIdx.x;
    int node = gid >> 4;
    int lane = gid & 15;
    if (node >= n) return;
    float eps1 = 1.0f + __ldg(eps_p);
    float acc = eps1 * __ldg(&x[(size_t)node * 16 + lane]);
    int s = g_rowptr[node], e = g_rowptr[node + 1];
    int i = s;
    for (; i + 4 <= e; i += 4) {
        int s0 = g_csr[i], s1 = g_csr[i + 1], s2 = g_csr[i + 2], s3 = g_csr[i + 3];
        acc += __ldg(&x[(size_t)s0 * 16 + lane]) + __ldg(&x[(size_t)s1 * 16 + lane]) +
               __ldg(&x[(size_t)s2 * 16 + lane]) + __ldg(&x[(size_t)s3 * 16 + lane]);
    }
    for (; i < e; i++) acc += __ldg(&x[(size_t)g_csr[i] * 16 + lane]);
    g_zh[(size_t)node * 16 + lane] = __float2half(acc);
}

// ---------------- aggregation H=128 (fp16 in/out) with fused BN affine ----------------
// z = s .* [ (1+eps)*u_self + sum u_nb ] + (1+eps+deg) * t,  s=gamma*rinv, t=beta-s*mean
__global__ void k_agg128(const __half* __restrict__ uh,
                         const float* __restrict__ gamma, const float* __restrict__ beta,
                         const float* __restrict__ bn, const float* __restrict__ eps_p,
                         float inv_n, int n) {
    int warp = (blockIdx.x * blockDim.x + threadIdx.x) >> 5;
    int lane = threadIdx.x & 31;
    if (warp >= n) return;
    int f0 = lane * 4;
    float4 ga = *(const float4*)&gamma[f0];
    float4 be = *(const float4*)&beta[f0];
    float m0 = bn[f0 + 0] * inv_n, m1 = bn[f0 + 1] * inv_n;
    float m2 = bn[f0 + 2] * inv_n, m3 = bn[f0 + 3] * inv_n;
    float r0 = rsqrtf(bn[128 + f0 + 0] * inv_n - m0 * m0 + BN_EPS);
    float r1 = rsqrtf(bn[128 + f0 + 1] * inv_n - m1 * m1 + BN_EPS);
    float r2 = rsqrtf(bn[128 + f0 + 2] * inv_n - m2 * m2 + BN_EPS);
    float r3 = rsqrtf(bn[128 + f0 + 3] * inv_n - m3 * m3 + BN_EPS);
    float s0 = ga.x * r0, t0 = be.x - s0 * m0;
    float s1 = ga.y * r1, t1 = be.y - s1 * m1;
    float s2 = ga.z * r2, t2 = be.z - s2 * m2;
    float s3 = ga.w * r3, t3 = be.w - s3 * m3;

    float eps1 = 1.0f + __ldg(eps_p);
    const uint2* uh2 = (const uint2*)uh;   // 4 halves per uint2
    uint2 sv = uh2[(size_t)warp * 32 + lane];
    float2 sp = __half22float2(*(__half2*)&sv.x), sq = __half22float2(*(__half2*)&sv.y);
    float ax = 0.f, ay = 0.f, az = 0.f, aw = 0.f;

    int sidx = g_rowptr[warp], eidx = g_rowptr[warp + 1];
    int i = sidx;
    for (; i + 4 <= eidx; i += 4) {
        int n0 = g_csr[i], n1 = g_csr[i + 1], n2 = g_csr[i + 2], n3 = g_csr[i + 3];
        uint2 v0 = uh2[(size_t)n0 * 32 + lane];
        uint2 v1 = uh2[(size_t)n1 * 32 + lane];
        uint2 v2 = uh2[(size_t)n2 * 32 + lane];
        uint2 v3 = uh2[(size_t)n3 * 32 + lane];
        float2 a01 = __half22float2(*(__half2*)&v0.x), a23 = __half22float2(*(__half2*)&v0.y);
        float2 b01 = __half22float2(*(__half2*)&v1.x), b23 = __half22float2(*(__half2*)&v1.y);
        float2 c01 = __half22float2(*(__half2*)&v2.x), c23 = __half22float2(*(__half2*)&v2.y);
        float2 d01 = __half22float2(*(__half2*)&v3.x), d23 = __half22float2(*(__half2*)&v3.y);
        ax += a01.x + b01.x + c01.x + d01.x;
        ay += a01.y + b01.y + c01.y + d01.y;
        az += a23.x + b23.x + c23.x + d23.x;
        aw += a23.y + b23.y + c23.y + d23.y;
    }
    for (; i < eidx; i++) {
        uint2 v = uh2[(size_t)g_csr[i] * 32 + lane];
        float2 p = __half22float2(*(__half2*)&v.x), q = __half22float2(*(__half2*)&v.y);
        ax += p.x; ay += p.y; az += q.x; aw += q.y;
    }
    float deg = (float)(eidx - sidx);
    float tc = eps1 + deg;
    float rx = s0 * (eps1 * sp.x + ax) + tc * t0;
    float ry = s1 * (eps1 * sp.y + ay) + tc * t1;
    float rz = s2 * (eps1 * sq.x + az) + tc * t2;
    float rw = s3 * (eps1 * sq.y + aw) + tc * t3;
    uint2 outv;
    *(__half2*)&outv.x = __floats2half2_rn(rx, ry);
    *(__half2*)&outv.y = __floats2half2_rn(rz, rw);
    ((uint2*)g_zh)[(size_t)warp * 32 + lane] = outv;
}

// ---------------- Tensor-core GEMM: C(fp16) = relu(A(fp16)[n x K] @ W(fp16)[K x 128] + b) ----------------
// BM=128, BN=128, BK=32, 256 threads (8 warps, 2x4), warp tile 64x32 via wmma 16x16x16
__global__ void __launch_bounds__(256)
k_gemm_tc(const __half* __restrict__ A, const __half* __restrict__ W,
          const float* __restrict__ bias, __half* __restrict__ Ch,
          float* __restrict__ bnslot, int n, int K) {
    __shared__ __half As[128][40];
    __shared__ __half Bs[32][136];
    __shared__ float Cbuf[32][132];
    __shared__ float sbn[256];

    int tid = threadIdx.x;
    int wid = tid >> 5;
    int warp_row = wid >> 2;       // 0..1 (64-row groups)
    int warp_col = wid & 3;        // 0..3 (32-col groups)
    int row0 = blockIdx.x * 128;

    wmma::fragment<wmma::accumulator, 16, 16, 16, float> acc[4][2];
#pragma unroll
    for (int r = 0; r < 4; r++)
#pragma unroll
        for (int c = 0; c < 2; c++) wmma::fill_fragment(acc[r][c], 0.0f);

    for (int kb = 0; kb < K; kb += 32) {
        // load A tile: 128 rows x 32 cols (halves); 512 uint4 loads
#pragma unroll
        for (int l = 0; l < 2; l++) {
            int idx = tid + l * 256;
            int row = idx >> 2;
            int col = (idx & 3) * 8;
            int gr = row0 + row;
            uint4 v = make_uint4(0, 0, 0, 0);
            if (gr < n && (kb + col) < K)
                v = *(const uint4*)&A[(size_t)gr * K + kb + col];
            *(uint4*)&As[row][col] = v;
        }
        // load B tile: 32 rows x 128 cols
#pragma unroll
        for (int l = 0; l < 2; l++) {
            int idx = tid + l * 256;
            int krow = idx >> 4;
            int col = (idx & 15) * 8;
            uint4 v = make_uint4(0, 0, 0, 0);
            if ((kb + krow) < K)
                v = *(const uint4*)&W[(size_t)(kb + krow) * 128 + col];
            *(uint4*)&Bs[krow][col] = v;
        }
        __syncthreads();
#pragma unroll
        for (int kk = 0; kk < 32; kk += 16) {
            wmma::fragment<wmma::matrix_a, 16, 16, 16, __half, wmma::row_major> af[4];
            wmma::fragment<wmma::matrix_b, 16, 16, 16, __half, wmma::row_major> bf[2];
#pragma unroll
            for (int r = 0; r < 4; r++)
                wmma::load_matrix_sync(af[r], &As[warp_row * 64 + r * 16][kk], 40);
#pragma unroll
            for (int c = 0; c < 2; c++)
                wmma::load_matrix_sync(bf[c], &Bs[kk][warp_col * 32 + c * 16], 136);
#pragma unroll
            for (int r = 0; r < 4; r++)
#pragma unroll
                for (int c = 0; c < 2; c++)
                    wmma::mma_sync(acc[r][c], af[r], bf[c], acc[r][c]);
        }
        __syncthreads();
    }

    // epilogue: 4 waves of 32 rows each through Cbuf
    int erow = tid >> 4;           // 0..15
    int ecg = tid & 15;            // col group of 8
    float bj[8];
#pragma unroll
    for (int j = 0; j < 8; j++) bj[j] = bias[ecg * 8 + j];
    float bs[8], bq[8];
#pragma unroll
    for (int j = 0; j < 8; j++) { bs[j] = 0.f; bq[j] = 0.f; }

    for (int v = 0; v < 4; v++) {
        if (warp_row == (v >> 1)) {
#pragma unroll
            for (int t = 0; t < 2; t++) {
                int fr = (v & 1) * 2 + t;
#pragma unroll
                for (int c = 0; c < 2; c++)
                    wmma::store_matrix_sync(&Cbuf[t * 16][warp_col * 32 + c * 16],
                                            acc[fr][c], 132, wmma::mem_row_major);
            }
        }
        __syncthreads();
#pragma unroll
        for (int it = 0; it < 2; it++) {
            int rw = erow + it * 16;
            int gr = row0 + v * 32 + rw;
            if (gr < n) {
                float vals[8];
#pragma unroll
                for (int j = 0; j < 8; j++) {
                    float z = fmaxf(Cbuf[rw][ecg * 8 + j] + bj[j], 0.0f);
                    vals[j] = z;
                    bs[j] += z;
                    bq[j] += z * z;
                }
                uint4 h;
                *(__half2*)&h.x = __floats2half2_rn(vals[0], vals[1]);
                *(__half2*)&h.y = __floats2half2_rn(vals[2], vals[3]);
                *(__half2*)&h.z = __floats2half2_rn(vals[4], vals[5]);
                *(__half2*)&h.w = __floats2half2_rn(vals[6], vals[7]);
                *(uint4*)&Ch[(size_t)gr * 128 + ecg * 8] = h;
            }
        }
        __syncthreads();
    }

    if (bnslot) {
        sbn[tid] = 0.0f;
        __syncthreads();
#pragma unroll
        for (int j = 0; j < 8; j++) {
            atomicAdd(&sbn[ecg * 8 + j], bs[j]);
            atomicAdd(&sbn[128 + ecg * 8 + j], bq[j]);
        }
        __syncthreads();
        atomicAdd(&bnslot[tid], sbn[tid]);
    }
}

// ---------------- per-graph mean pool of fp16 embeddings (batch sorted) ----------------
__global__ void k_pool(const int* __restrict__ batch, int n) {
    int f = threadIdx.x;            // 0..511 ; feature = slab*128 + col
    int slab = f >> 7, col = f & 127;
    int chunk = (n + gridDim.x - 1) / gridDim.x;
    int start = blockIdx.x * chunk;
    int end = min(start + chunk, n);
    if (start >= end) return;
    const __half* base = g_embh + (size_t)slab * NMAX * HDIM;
    float acc = 0.f;
    int cnt = 0;
    int cur = batch[start];
    for (int i = start; i < end; i++) {
        int g = batch[i];
        if (g != cur) {
            atomicAdd(&g_pool[cur * 512 + f], acc);
            if (f == 0) atomicAdd(&g_cnt[cur], (float)cnt);
            acc = 0.f; cnt = 0; cur = g;
        }
        acc += __half2float(base[(size_t)i * 128 + col]);
        cnt++;
    }
    atomicAdd(&g_pool[cur * 512 + f], acc);
    if (f == 0) atomicAdd(&g_cnt[cur], (float)cnt);
}

// ---------------- classifier with BN affine on pooled means ----------------
__global__ void k_classifier(const float* __restrict__ W1, const float* __restrict__ b1,
                             const float* __restrict__ W2, const float* __restrict__ b2,
                             const float* __restrict__ W3, const float* __restrict__ b3,
                             const float* __restrict__ W4, const float* __restrict__ b4,
                             const float* __restrict__ c1g, const float* __restrict__ c1b,
                             const float* __restrict__ cg, const float* __restrict__ cb,
                             float inv_n, float* __restrict__ out) {
    __shared__ float emb[512], h1[256], h2[128], h3[128], logits[10];
    int g = blockIdx.x;
    int tid = threadIdx.x;   // 256 threads
    float cnt = fmaxf(g_cnt[g], 1.0f);
    for (int f = tid; f < 512; f += 256) {
        int slab = f >> 7, col = f & 127;
        const float* G = (slab == 0) ? c1g : cg + (slab - 1) * 128;
        const float* B = (slab == 0) ? c1b : cb + (slab - 1) * 128;
        float m = g_bn[slab * 256 + col] * inv_n;
        float r = rsqrtf(g_bn[slab * 256 + 128 + col] * inv_n - m * m + BN_EPS);
        float s = G[col] * r;
        float t = B[col] - s * m;
        emb[f] = s * (g_pool[g * 512 + f] / cnt) + t;
    }
    __syncthreads();
    {
        float a = b1[tid];
        for (int k = 0; k < 512; k++) a += emb[k] * W1[k * 256 + tid];
        h1[tid] = fmaxf(a, 0.f);
    }
    __syncthreads();
    if (tid < 128) {
        float a = b2[tid];
        for (int k = 0; k < 256; k++) a += h1[k] * W2[k * 128 + tid];
        h2[tid] = fmaxf(a, 0.f);
    }
    __syncthreads();
    if (tid < 128) {
        float a = b3[tid];
        for (int k = 0; k < 128; k++) a += h2[k] * W3[k * 128 + tid];
        h3[tid] = fmaxf(a, 0.f);
    }
    __syncthreads();
    if (tid < 10) {
        float a = b4[tid];
        for (int k = 0; k < 128; k++) a += h3[k] * W4[k * 10 + tid];
        logits[tid] = a;
    }
    __syncthreads();
    if (tid == 0) {
        float mx = logits[0];
        for (int c = 1; c < 10; c++) mx = fmaxf(mx, logits[c]);
        float se = 0.f;
        for (int c = 0; c < 10; c++) se += expf(logits[c] - mx);
        float lse = logf(se) + mx;
        for (int c = 0; c < 10; c++) out[g * 10 + c] = logits[c] - lse;
    }
}

// ---------------- launch orchestration ----------------
extern "C" void kernel_launch(void* const* d_in, const int* in_sizes, int n_in,
                              void* d_out, int out_size) {
    const float* x     = (const float*)d_in[0];
    const int*   ei    = (const int*)d_in[1];
    const int*   batch = (const int*)d_in[2];
    const float* c1W1 = (const float*)d_in[3];
    const float* c1b1 = (const float*)d_in[4];
    const float* c1W2 = (const float*)d_in[5];
    const float* c1b2 = (const float*)d_in[6];
    const float* c1g  = (const float*)d_in[7];
    const float* c1b  = (const float*)d_in[8];
    const float* c1e  = (const float*)d_in[9];
    const float* cW1  = (const float*)d_in[10];
    const float* cb1  = (const float*)d_in[11];
    const float* cW2  = (const float*)d_in[12];
    const float* cb2  = (const float*)d_in[13];
    const float* cg   = (const float*)d_in[14];
    const float* cb   = (const float*)d_in[15];
    const float* ce   = (const float*)d_in[16];
    const float* lW1 = (const float*)d_in[17];
    const float* lb1 = (const float*)d_in[18];
    const float* lW2 = (const float*)d_in[19];
    const float* lb2 = (const float*)d_in[20];
    const float* lW3 = (const float*)d_in[21];
    const float* lb3 = (const float*)d_in[22];
    const float* lW4 = (const float*)d_in[23];
    const float* lb4 = (const float*)d_in[24];
    float* out = (float*)d_out;

    int n = in_sizes[0] / 16;
    int e = in_sizes[1] / 2;
    if (n > NMAX) n = NMAX;
    if (e > EMAX) e = EMAX;
    const int* src = ei;
    const int* dst = ei + e;
    float inv_n = 1.0f / (float)n;

    __half* zh_ptr;   cudaGetSymbolAddress((void**)&zh_ptr, g_zh);
    __half* th_ptr;   cudaGetSymbolAddress((void**)&th_ptr, g_th);
    __half* embh_ptr; cudaGetSymbolAddress((void**)&embh_ptr, g_embh);
    __half* wh_ptr;   cudaGetSymbolAddress((void**)&wh_ptr, g_wh);
    float*  bn_ptr;   cudaGetSymbolAddress((void**)&bn_ptr, g_bn);

    k_zero<<<256, 256>>>(n);
    k_wconv<<<512, 256>>>(c1W1, c1W2, cW1, cW2);
    k_count<<<(e + 255) / 256, 256>>>(dst, e);

    int chunk = (n + SCAN_NB - 1) / SCAN_NB;
    int tch = (chunk + 255) / 256;
    k_scan1<<<SCAN_NB, 256>>>(n, chunk, tch);
    k_scan2<<<1, 256>>>(n);
    k_scan3<<<SCAN_NB, 256>>>(n, chunk, tch);

    k_fill<<<(e + 255) / 256, 256>>>(src, dst, e);

    int gemm_blocks = (n + 127) / 128;

    // Layer 1 (F=16 input)
    k_agg16<<<(n * 16 + 255) / 256, 256>>>(x, c1e, n);
    k_gemm_tc<<<gemm_blocks, 256>>>(zh_ptr, wh_ptr + 0 * 16384, c1b1, th_ptr,
                                    (float*)nullptr, n, 16);
    k_gemm_tc<<<gemm_blocks, 256>>>(th_ptr, wh_ptr + 1 * 16384, c1b2, embh_ptr,
                                    bn_ptr, n, 128);

    // Layers 2-4
    for (int l = 1; l < 4; l++) {
        int i = l - 1;
        const float* gprev = (l == 1) ? c1g : cg + (l - 2) * 128;
        const float* bprev = (l == 1) ? c1b : cb + (l - 2) * 128;
        k_agg128<<<(n * 32 + 255) / 256, 256>>>(
            embh_ptr + (size_t)(l - 1) * NMAX * HDIM,
            gprev, bprev, bn_ptr + (l - 1) * 256, ce + i, inv_n, n);
        k_gemm_tc<<<gemm_blocks, 256>>>(zh_ptr, wh_ptr + (2 + 2 * i) * 16384, cb1 + i * 128,
                                        th_ptr, (float*)nullptr, n, 128);
        k_gemm_tc<<<gemm_blocks, 256>>>(th_ptr, wh_ptr + (3 + 2 * i) * 16384, cb2 + i * 128,
                                        embh_ptr + (size_t)l * NMAX * HDIM,
                                        bn_ptr + l * 256, n, 128);
    }

    k_pool<<<200, 512>>>(batch, n);
    k_classifier<<<NGRAPH, 256>>>(lW1, lb1, lW2, lb2, lW3, lb3, lW4, lb4,
                                  c1g, c1b, cg, cb, inv_n, out);
}

// round 6
// speedup vs baseline: 2.2493x; 1.0458x over previous
#include <cuda_runtime.h>
#include <cuda_fp16.h>
#include <mma.h>
#include <math.h>

using namespace nvcuda;

#define NMAX 100000
#define EMAX 1600000
#define HDIM 128
#define NGRAPH 64
#define BN_EPS 1e-5f
#define SCAN_NB 240

// dynamic smem layout for fused MLP kernel
#define MLP_AS_OFF   0              // As [128][40] half (10240 B)  -- aliased with Cbuf
#define MLP_CBUF_OFF 0              // Cbuf [32][132] float (16896 B)
#define MLP_BS_OFF   16896          // Bs [32][136] half (8704 B)
#define MLP_T_OFF    25600          // T  [128][136] half (34816 B)
#define MLP_SBN_OFF  60416          // sbn [256] float (1024 B)
#define MLP_SMEM     61440

// ---------------- static device scratch ----------------
__device__ __half g_embh[4ll * NMAX * HDIM];   // fp16 layer outputs (pre-BN)
__device__ __half g_zh[(size_t)NMAX * HDIM];   // aggregation output (MLP input)
__device__ __half g_wh[8 * 16384];             // fp16 weights: slot*16384
__device__ int    g_deg[NMAX];
__device__ int    g_cursor[NMAX];
__device__ int    g_rowptr[NMAX + 1];
__device__ int    g_csr[EMAX];
__device__ int    g_bsum[SCAN_NB];
__device__ float  g_bn[4 * 256];               // per layer: [0..127]=sum, [128..255]=sumsq
__device__ float  g_pool[NGRAPH * 512];
__device__ float  g_cnt[NGRAPH];

// ---------------- zero ----------------
__global__ void k_zero(int n) {
    int i = blockIdx.x * blockDim.x + threadIdx.x;
    int stride = gridDim.x * blockDim.x;
    for (int j = i; j < n; j += stride) { g_deg[j] = 0; g_cursor[j] = 0; }
    for (int j = i; j < 4 * 256; j += stride) g_bn[j] = 0.0f;
    for (int j = i; j < NGRAPH * 512; j += stride) g_pool[j] = 0.0f;
    for (int j = i; j < NGRAPH; j += stride) g_cnt[j] = 0.0f;
}

// ---------------- weight conversion to fp16 ----------------
__global__ void k_wconv(const float* __restrict__ c1W1, const float* __restrict__ c1W2,
                        const float* __restrict__ cW1, const float* __restrict__ cW2) {
    int idx = blockIdx.x * blockDim.x + threadIdx.x;
    if (idx >= 8 * 16384) return;
    int slot = idx >> 14;
    int off = idx & 16383;
    float v = 0.0f;
    if (slot == 0) { if (off < 2048) v = c1W1[off]; }
    else if (slot == 1) v = c1W2[off];
    else {
        int i = (slot - 2) >> 1;
        v = (slot & 1) ? cW2[i * 16384 + off] : cW1[i * 16384 + off];
    }
    g_wh[idx] = __float2half(v);
}

// ---------------- CSR build ----------------
__global__ void k_count(const int* __restrict__ dst, int e) {
    int i = blockIdx.x * blockDim.x + threadIdx.x;
    if (i < e) atomicAdd(&g_deg[dst[i]], 1);
}

__global__ void k_scan1(int n, int chunk, int tch) {
    __shared__ int s[256];
    int tid = threadIdx.x;
    int bstart = blockIdx.x * chunk;
    int bend = min(bstart + chunk, n);
    int start = bstart + tid * tch;
    int end = min(start + tch, bend);
    int sum = 0;
    for (int i = start; i < end; i++) sum += g_deg[i];
    s[tid] = sum;
    __syncthreads();
    for (int off = 128; off > 0; off >>= 1) {
        if (tid < off) s[tid] += s[tid + off];
        __syncthreads();
    }
    if (tid == 0) g_bsum[blockIdx.x] = s[0];
}

__global__ void k_scan2(int n) {
    __shared__ int s[SCAN_NB];
    int tid = threadIdx.x;
    int v = (tid < SCAN_NB) ? g_bsum[tid] : 0;
    if (tid < SCAN_NB) s[tid] = v;
    __syncthreads();
    for (int off = 1; off < SCAN_NB; off <<= 1) {
        int t = (tid < SCAN_NB && tid >= off) ? s[tid - off] : 0;
        __syncthreads();
        if (tid < SCAN_NB) s[tid] += t;
        __syncthreads();
    }
    if (tid < SCAN_NB) g_bsum[tid] = s[tid] - v;
    if (tid == SCAN_NB - 1) g_rowptr[n] = s[tid];
}

__global__ void k_scan3(int n, int chunk, int tch) {
    __shared__ int s[256];
    int tid = threadIdx.x;
    int bstart = blockIdx.x * chunk;
    int bend = min(bstart + chunk, n);
    int start = bstart + tid * tch;
    int end = min(start + tch, bend);
    int sum = 0;
    for (int i = start; i < end; i++) sum += g_deg[i];
    s[tid] = sum;
    __syncthreads();
    for (int off = 1; off < 256; off <<= 1) {
        int t = (tid >= off) ? s[tid - off] : 0;
        __syncthreads();
        s[tid] += t;
        __syncthreads();
    }
    int base = g_bsum[blockIdx.x] + s[tid] - sum;
    for (int i = start; i < end; i++) { g_rowptr[i] = base; base += g_deg[i]; }
}

__global__ void k_fill(const int* __restrict__ src, const int* __restrict__ dst, int e) {
    int i = blockIdx.x * blockDim.x + threadIdx.x;
    if (i < e) {
        int d = dst[i];
        int pos = atomicAdd(&g_cursor[d], 1);
        g_csr[g_rowptr[d] + pos] = src[i];
    }
}

// ---------------- aggregation, layer 1 (F=16, raw x) -> fp16 z ----------------
__global__ void k_agg16(const float* __restrict__ x, const float* __restrict__ eps_p, int n) {
    int gid = blockIdx.x * blockDim.x + threadIdx.x;
    int node = gid >> 4;
    int lane = gid & 15;
    if (node >= n) return;
    float eps1 = 1.0f + __ldg(eps_p);
    float acc = eps1 * __ldg(&x[(size_t)node * 16 + lane]);
    int s = g_rowptr[node], e = g_rowptr[node + 1];
    int i = s;
    for (; i + 4 <= e; i += 4) {
        int s0 = g_csr[i], s1 = g_csr[i + 1], s2 = g_csr[i + 2], s3 = g_csr[i + 3];
        acc += __ldg(&x[(size_t)s0 * 16 + lane]) + __ldg(&x[(size_t)s1 * 16 + lane]) +
               __ldg(&x[(size_t)s2 * 16 + lane]) + __ldg(&x[(size_t)s3 * 16 + lane]);
    }
    for (; i < e; i++) acc += __ldg(&x[(size_t)g_csr[i] * 16 + lane]);
    g_zh[(size_t)node * 16 + lane] = __float2half(acc);
}

// ---------------- aggregation H=128 (fp16 in/out) with fused BN affine ----------------
__global__ void k_agg128(const __half* __restrict__ uh,
                         const float* __restrict__ gamma, const float* __restrict__ beta,
                         const float* __restrict__ bn, const float* __restrict__ eps_p,
                         float inv_n, int n) {
    int warp = (blockIdx.x * blockDim.x + threadIdx.x) >> 5;
    int lane = threadIdx.x & 31;
    if (warp >= n) return;
    int f0 = lane * 4;
    float4 ga = *(const float4*)&gamma[f0];
    float4 be = *(const float4*)&beta[f0];
    float m0 = bn[f0 + 0] * inv_n, m1 = bn[f0 + 1] * inv_n;
    float m2 = bn[f0 + 2] * inv_n, m3 = bn[f0 + 3] * inv_n;
    float r0 = rsqrtf(bn[128 + f0 + 0] * inv_n - m0 * m0 + BN_EPS);
    float r1 = rsqrtf(bn[128 + f0 + 1] * inv_n - m1 * m1 + BN_EPS);
    float r2 = rsqrtf(bn[128 + f0 + 2] * inv_n - m2 * m2 + BN_EPS);
    float r3 = rsqrtf(bn[128 + f0 + 3] * inv_n - m3 * m3 + BN_EPS);
    float s0 = ga.x * r0, t0 = be.x - s0 * m0;
    float s1 = ga.y * r1, t1 = be.y - s1 * m1;
    float s2 = ga.z * r2, t2 = be.z - s2 * m2;
    float s3 = ga.w * r3, t3 = be.w - s3 * m3;

    float eps1 = 1.0f + __ldg(eps_p);
    const uint2* uh2 = (const uint2*)uh;
    uint2 sv = uh2[(size_t)warp * 32 + lane];
    float2 sp = __half22float2(*(__half2*)&sv.x), sq = __half22float2(*(__half2*)&sv.y);
    float ax = 0.f, ay = 0.f, az = 0.f, aw = 0.f;

    int sidx = g_rowptr[warp], eidx = g_rowptr[warp + 1];
    int i = sidx;
    for (; i + 4 <= eidx; i += 4) {
        int n0 = g_csr[i], n1 = g_csr[i + 1], n2 = g_csr[i + 2], n3 = g_csr[i + 3];
        uint2 v0 = uh2[(size_t)n0 * 32 + lane];
        uint2 v1 = uh2[(size_t)n1 * 32 + lane];
        uint2 v2 = uh2[(size_t)n2 * 32 + lane];
        uint2 v3 = uh2[(size_t)n3 * 32 + lane];
        float2 a01 = __half22float2(*(__half2*)&v0.x), a23 = __half22float2(*(__half2*)&v0.y);
        float2 b01 = __half22float2(*(__half2*)&v1.x), b23 = __half22float2(*(__half2*)&v1.y);
        float2 c01 = __half22float2(*(__half2*)&v2.x), c23 = __half22float2(*(__half2*)&v2.y);
        float2 d01 = __half22float2(*(__half2*)&v3.x), d23 = __half22float2(*(__half2*)&v3.y);
        ax += a01.x + b01.x + c01.x + d01.x;
        ay += a01.y + b01.y + c01.y + d01.y;
        az += a23.x + b23.x + c23.x + d23.x;
        aw += a23.y + b23.y + c23.y + d23.y;
    }
    for (; i < eidx; i++) {
        uint2 v = uh2[(size_t)g_csr[i] * 32 + lane];
        float2 p = __half22float2(*(__half2*)&v.x), q = __half22float2(*(__half2*)&v.y);
        ax += p.x; ay += p.y; az += q.x; aw += q.y;
    }
    float deg = (float)(eidx - sidx);
    float tc = eps1 + deg;
    float rx = s0 * (eps1 * sp.x + ax) + tc * t0;
    float ry = s1 * (eps1 * sp.y + ay) + tc * t1;
    float rz = s2 * (eps1 * sq.x + az) + tc * t2;
    float rw = s3 * (eps1 * sq.y + aw) + tc * t3;
    uint2 outv;
    *(__half2*)&outv.x = __floats2half2_rn(rx, ry);
    *(__half2*)&outv.y = __floats2half2_rn(rz, rw);
    ((uint2*)g_zh)[(size_t)warp * 32 + lane] = outv;
}

// ---------------- Fused MLP: C = relu(relu(A@W1+b1)@W2+b2), fp16 TC, BN stats ----------------
// BM=128, threads=256 (8 warps 2x4), warp tile 64x32; intermediate T kept in smem.
__global__ void __launch_bounds__(256)
k_mlp_tc(const __half* __restrict__ A, const __half* __restrict__ W1,
         const float* __restrict__ b1, const __half* __restrict__ W2,
         const float* __restrict__ b2, __half* __restrict__ Ch,
         float* __restrict__ bnslot, int n, int K1) {
    extern __shared__ char smem[];
    __half (*As)[40]    = (__half(*)[40])(smem + MLP_AS_OFF);
    float  (*Cbuf)[132] = (float(*)[132])(smem + MLP_CBUF_OFF);
    __half (*Bs)[136]   = (__half(*)[136])(smem + MLP_BS_OFF);
    __half (*T)[136]    = (__half(*)[136])(smem + MLP_T_OFF);
    float  *sbn         = (float*)(smem + MLP_SBN_OFF);

    int tid = threadIdx.x;
    int wid = tid >> 5;
    int warp_row = wid >> 2;       // 0..1
    int warp_col = wid & 3;        // 0..3
    int row0 = blockIdx.x * 128;
    int erow = tid >> 4;           // 0..15
    int ecg = tid & 15;            // col group of 8

    wmma::fragment<wmma::accumulator, 16, 16, 16, float> acc[4][2];
#pragma unroll
    for (int r = 0; r < 4; r++)
#pragma unroll
        for (int c = 0; c < 2; c++) wmma::fill_fragment(acc[r][c], 0.0f);

    // ---------- stage 1: T = relu(A @ W1 + b1) ----------
    for (int kb = 0; kb < K1; kb += 32) {
#pragma unroll
        for (int l = 0; l < 2; l++) {
            int idx = tid + l * 256;
            int row = idx >> 2;
            int col = (idx & 3) * 8;
            int gr = row0 + row;
            uint4 v = make_uint4(0, 0, 0, 0);
            if (gr < n && (kb + col) < K1)
                v = *(const uint4*)&A[(size_t)gr * K1 + kb + col];
            *(uint4*)&As[row][col] = v;
        }
#pragma unroll
        for (int l = 0; l < 2; l++) {
            int idx = tid + l * 256;
            int krow = idx >> 4;
            int col = (idx & 15) * 8;
            uint4 v = make_uint4(0, 0, 0, 0);
            if ((kb + krow) < K1)
                v = *(const uint4*)&W1[(size_t)(kb + krow) * 128 + col];
            *(uint4*)&Bs[krow][col] = v;
        }
        __syncthreads();
#pragma unroll
        for (int kk = 0; kk < 32; kk += 16) {
            wmma::fragment<wmma::matrix_a, 16, 16, 16, __half, wmma::row_major> af[4];
            wmma::fragment<wmma::matrix_b, 16, 16, 16, __half, wmma::row_major> bf[2];
#pragma unroll
            for (int r = 0; r < 4; r++)
                wmma::load_matrix_sync(af[r], &As[warp_row * 64 + r * 16][kk], 40);
#pragma unroll
            for (int c = 0; c < 2; c++)
                wmma::load_matrix_sync(bf[c], &Bs[kk][warp_col * 32 + c * 16], 136);
#pragma unroll
            for (int r = 0; r < 4; r++)
#pragma unroll
                for (int c = 0; c < 2; c++)
                    wmma::mma_sync(acc[r][c], af[r], bf[c], acc[r][c]);
        }
        __syncthreads();
    }

    // stage-1 epilogue: bias1+relu -> fp16 T in smem (4 waves of 32 rows via Cbuf)
    {
        float bj[8];
#pragma unroll
        for (int j = 0; j < 8; j++) bj[j] = b1[ecg * 8 + j];
        for (int v = 0; v < 4; v++) {
            if (warp_row == (v >> 1)) {
#pragma unroll
                for (int t = 0; t < 2; t++) {
                    int fr = (v & 1) * 2 + t;
#pragma unroll
                    for (int c = 0; c < 2; c++)
                        wmma::store_matrix_sync(&Cbuf[t * 16][warp_col * 32 + c * 16],
                                                acc[fr][c], 132, wmma::mem_row_major);
                }
            }
            __syncthreads();
#pragma unroll
            for (int it = 0; it < 2; it++) {
                int rw = erow + it * 16;
                float z0 = fmaxf(Cbuf[rw][ecg * 8 + 0] + bj[0], 0.0f);
                float z1 = fmaxf(Cbuf[rw][ecg * 8 + 1] + bj[1], 0.0f);
                float z2 = fmaxf(Cbuf[rw][ecg * 8 + 2] + bj[2], 0.0f);
                float z3 = fmaxf(Cbuf[rw][ecg * 8 + 3] + bj[3], 0.0f);
                float z4 = fmaxf(Cbuf[rw][ecg * 8 + 4] + bj[4], 0.0f);
                float z5 = fmaxf(Cbuf[rw][ecg * 8 + 5] + bj[5], 0.0f);
                float z6 = fmaxf(Cbuf[rw][ecg * 8 + 6] + bj[6], 0.0f);
                float z7 = fmaxf(Cbuf[rw][ecg * 8 + 7] + bj[7], 0.0f);
                uint4 h;
                *(__half2*)&h.x = __floats2half2_rn(z0, z1);
                *(__half2*)&h.y = __floats2half2_rn(z2, z3);
                *(__half2*)&h.z = __floats2half2_rn(z4, z5);
                *(__half2*)&h.w = __floats2half2_rn(z6, z7);
                *(uint4*)&T[v * 32 + rw][ecg * 8] = h;
            }
            __syncthreads();
        }
    }

    // ---------- stage 2: C = relu(T @ W2 + b2) ----------
#pragma unroll
    for (int r = 0; r < 4; r++)
#pragma unroll
        for (int c = 0; c < 2; c++) wmma::fill_fragment(acc[r][c], 0.0f);

    for (int kb = 0; kb < 128; kb += 32) {
#pragma unroll
        for (int l = 0; l < 2; l++) {
            int idx = tid + l * 256;
            int krow = idx >> 4;
            int col = (idx & 15) * 8;
            *(uint4*)&Bs[krow][col] = *(const uint4*)&W2[(size_t)(kb + krow) * 128 + col];
        }
        __syncthreads();
#pragma unroll
        for (int kk = 0; kk < 32; kk += 16) {
            wmma::fragment<wmma::matrix_a, 16, 16, 16, __half, wmma::row_major> af[4];
            wmma::fragment<wmma::matrix_b, 16, 16, 16, __half, wmma::row_major> bf[2];
#pragma unroll
            for (int r = 0; r < 4; r++)
                wmma::load_matrix_sync(af[r], &T[warp_row * 64 + r * 16][kb + kk], 136);
#pragma unroll
            for (int c = 0; c < 2; c++)
                wmma::load_matrix_sync(bf[c], &Bs[kk][warp_col * 32 + c * 16], 136);
#pragma unroll
            for (int r = 0; r < 4; r++)
#pragma unroll
                for (int c = 0; c < 2; c++)
                    wmma::mma_sync(acc[r][c], af[r], bf[c], acc[r][c]);
        }
        __syncthreads();
    }

    // stage-2 epilogue: bias2+relu -> global fp16 + BN stats
    float bj[8];
#pragma unroll
    for (int j = 0; j < 8; j++) bj[j] = b2[ecg * 8 + j];
    float bsm[8], bq[8];
#pragma unroll
    for (int j = 0; j < 8; j++) { bsm[j] = 0.f; bq[j] = 0.f; }

    for (int v = 0; v < 4; v++) {
        if (warp_row == (v >> 1)) {
#pragma unroll
            for (int t = 0; t < 2; t++) {
                int fr = (v & 1) * 2 + t;
#pragma unroll
                for (int c = 0; c < 2; c++)
                    wmma::store_matrix_sync(&Cbuf[t * 16][warp_col * 32 + c * 16],
                                            acc[fr][c], 132, wmma::mem_row_major);
            }
        }
        __syncthreads();
#pragma unroll
        for (int it = 0; it < 2; it++) {
            int rw = erow + it * 16;
            int gr = row0 + v * 32 + rw;
            if (gr < n) {
                float vals[8];
#pragma unroll
                for (int j = 0; j < 8; j++) {
                    float z = fmaxf(Cbuf[rw][ecg * 8 + j] + bj[j], 0.0f);
                    vals[j] = z;
                    bsm[j] += z;
                    bq[j] += z * z;
                }
                uint4 h;
                *(__half2*)&h.x = __floats2half2_rn(vals[0], vals[1]);
                *(__half2*)&h.y = __floats2half2_rn(vals[2], vals[3]);
                *(__half2*)&h.z = __floats2half2_rn(vals[4], vals[5]);
                *(__half2*)&h.w = __floats2half2_rn(vals[6], vals[7]);
                *(uint4*)&Ch[(size_t)gr * 128 + ecg * 8] = h;
            }
        }
        __syncthreads();
    }

    sbn[tid] = 0.0f;
    __syncthreads();
#pragma unroll
    for (int j = 0; j < 8; j++) {
        atomicAdd(&sbn[ecg * 8 + j], bsm[j]);
        atomicAdd(&sbn[128 + ecg * 8 + j], bq[j]);
    }
    __syncthreads();
    atomicAdd(&bnslot[tid], sbn[tid]);
}

// ---------------- per-graph mean pool of fp16 embeddings (batch sorted) ----------------
__global__ void k_pool(const int* __restrict__ batch, int n) {
    int f = threadIdx.x;
    int slab = f >> 7, col = f & 127;
    int chunk = (n + gridDim.x - 1) / gridDim.x;
    int start = blockIdx.x * chunk;
    int end = min(start + chunk, n);
    if (start >= end) return;
    const __half* base = g_embh + (size_t)slab * NMAX * HDIM;
    float acc = 0.f;
    int cnt = 0;
    int cur = batch[start];
    for (int i = start; i < end; i++) {
        int g = batch[i];
        if (g != cur) {
            atomicAdd(&g_pool[cur * 512 + f], acc);
            if (f == 0) atomicAdd(&g_cnt[cur], (float)cnt);
            acc = 0.f; cnt = 0; cur = g;
        }
        acc += __half2float(base[(size_t)i * 128 + col]);
        cnt++;
    }
    atomicAdd(&g_pool[cur * 512 + f], acc);
    if (f == 0) atomicAdd(&g_cnt[cur], (float)cnt);
}

// ---------------- classifier with BN affine on pooled means ----------------
__global__ void k_classifier(const float* __restrict__ W1, const float* __restrict__ b1,
                             const float* __restrict__ W2, const float* __restrict__ b2,
                             const float* __restrict__ W3, const float* __restrict__ b3,
                             const float* __restrict__ W4, const float* __restrict__ b4,
                             const float* __restrict__ c1g, const float* __restrict__ c1b,
                             const float* __restrict__ cg, const float* __restrict__ cb,
                             float inv_n, float* __restrict__ out) {
    __shared__ float emb[512], h1[256], h2[128], h3[128], logits[10];
    int g = blockIdx.x;
    int tid = threadIdx.x;
    float cnt = fmaxf(g_cnt[g], 1.0f);
    for (int f = tid; f < 512; f += 256) {
        int slab = f >> 7, col = f & 127;
        const float* G = (slab == 0) ? c1g : cg + (slab - 1) * 128;
        const float* B = (slab == 0) ? c1b : cb + (slab - 1) * 128;
        float m = g_bn[slab * 256 + col] * inv_n;
        float r = rsqrtf(g_bn[slab * 256 + 128 + col] * inv_n - m * m + BN_EPS);
        float s = G[col] * r;
        float t = B[col] - s * m;
        emb[f] = s * (g_pool[g * 512 + f] / cnt) + t;
    }
    __syncthreads();
    {
        float a = b1[tid];
        for (int k = 0; k < 512; k++) a += emb[k] * W1[k * 256 + tid];
        h1[tid] = fmaxf(a, 0.f);
    }
    __syncthreads();
    if (tid < 128) {
        float a = b2[tid];
        for (int k = 0; k < 256; k++) a += h1[k] * W2[k * 128 + tid];
        h2[tid] = fmaxf(a, 0.f);
    }
    __syncthreads();
    if (tid < 128) {
        float a = b3[tid];
        for (int k = 0; k < 128; k++) a += h2[k] * W3[k * 128 + tid];
        h3[tid] = fmaxf(a, 0.f);
    }
    __syncthreads();
    if (tid < 10) {
        float a = b4[tid];
        for (int k = 0; k < 128; k++) a += h3[k] * W4[k * 10 + tid];
        logits[tid] = a;
    }
    __syncthreads();
    if (tid == 0) {
        float mx = logits[0];
        for (int c = 1; c < 10; c++) mx = fmaxf(mx, logits[c]);
        float se = 0.f;
        for (int c = 0; c < 10; c++) se += expf(logits[c] - mx);
        float lse = logf(se) + mx;
        for (int c = 0; c < 10; c++) out[g * 10 + c] = logits[c] - lse;
    }
}

// ---------------- launch orchestration ----------------
extern "C" void kernel_launch(void* const* d_in, const int* in_sizes, int n_in,
                              void* d_out, int out_size) {
    const float* x     = (const float*)d_in[0];
    const int*   ei    = (const int*)d_in[1];
    const int*   batch = (const int*)d_in[2];
    const float* c1W1 = (const float*)d_in[3];
    const float* c1b1 = (const float*)d_in[4];
    const float* c1W2 = (const float*)d_in[5];
    const float* c1b2 = (const float*)d_in[6];
    const float* c1g  = (const float*)d_in[7];
    const float* c1b  = (const float*)d_in[8];
    const float* c1e  = (const float*)d_in[9];
    const float* cW1  = (const float*)d_in[10];
    const float* cb1  = (const float*)d_in[11];
    const float* cW2  = (const float*)d_in[12];
    const float* cb2  = (const float*)d_in[13];
    const float* cg   = (const float*)d_in[14];
    const float* cb   = (const float*)d_in[15];
    const float* ce   = (const float*)d_in[16];
    const float* lW1 = (const float*)d_in[17];
    const float* lb1 = (const float*)d_in[18];
    const float* lW2 = (const float*)d_in[19];
    const float* lb2 = (const float*)d_in[20];
    const float* lW3 = (const float*)d_in[21];
    const float* lb3 = (const float*)d_in[22];
    const float* lW4 = (const float*)d_in[23];
    const float* lb4 = (const float*)d_in[24];
    float* out = (float*)d_out;

    int n = in_sizes[0] / 16;
    int e = in_sizes[1] / 2;
    if (n > NMAX) n = NMAX;
    if (e > EMAX) e = EMAX;
    const int* src = ei;
    const int* dst = ei + e;
    float inv_n = 1.0f / (float)n;

    __half* zh_ptr;   cudaGetSymbolAddress((void**)&zh_ptr, g_zh);
    __half* embh_ptr; cudaGetSymbolAddress((void**)&embh_ptr, g_embh);
    __half* wh_ptr;   cudaGetSymbolAddress((void**)&wh_ptr, g_wh);
    float*  bn_ptr;   cudaGetSymbolAddress((void**)&bn_ptr, g_bn);

    static int smem_set = 0;
    if (!smem_set) {
        cudaFuncSetAttribute(k_mlp_tc, cudaFuncAttributeMaxDynamicSharedMemorySize, MLP_SMEM);
        smem_set = 1;
    }

    k_zero<<<256, 256>>>(n);
    k_wconv<<<512, 256>>>(c1W1, c1W2, cW1, cW2);
    k_count<<<(e + 255) / 256, 256>>>(dst, e);

    int chunk = (n + SCAN_NB - 1) / SCAN_NB;
    int tch = (chunk + 255) / 256;
    k_scan1<<<SCAN_NB, 256>>>(n, chunk, tch);
    k_scan2<<<1, 256>>>(n);
    k_scan3<<<SCAN_NB, 256>>>(n, chunk, tch);

    k_fill<<<(e + 255) / 256, 256>>>(src, dst, e);

    int gemm_blocks = (n + 127) / 128;

    // Layer 1 (F=16 input)
    k_agg16<<<(n * 16 + 255) / 256, 256>>>(x, c1e, n);
    k_mlp_tc<<<gemm_blocks, 256, MLP_SMEM>>>(zh_ptr, wh_ptr + 0 * 16384, c1b1,
                                             wh_ptr + 1 * 16384, c1b2,
                                             embh_ptr, bn_ptr, n, 16);

    // Layers 2-4
    for (int l = 1; l < 4; l++) {
        int i = l - 1;
        const float* gprev = (l == 1) ? c1g : cg + (l - 2) * 128;
        const float* bprev = (l == 1) ? c1b : cb + (l - 2) * 128;
        k_agg128<<<(n * 32 + 255) / 256, 256>>>(
            embh_ptr + (size_t)(l - 1) * NMAX * HDIM,
            gprev, bprev, bn_ptr + (l - 1) * 256, ce + i, inv_n, n);
        k_mlp_tc<<<gemm_blocks, 256, MLP_SMEM>>>(zh_ptr, wh_ptr + (2 + 2 * i) * 16384, cb1 + i * 128,
                                                 wh_ptr + (3 + 2 * i) * 16384, cb2 + i * 128,
                                                 embh_ptr + (size_t)l * NMAX * HDIM,
                                                 bn_ptr + l * 256, n, 128);
    }

    k_pool<<<200, 512>>>(batch, n);
    k_classifier<<<NGRAPH, 256>>>(lW1, lb1, lW2, lb2, lW3, lb3, lW4, lb4,
                                  c1g, c1b, cg, cb, inv_n, out);
}